// round 1
// baseline (speedup 1.0000x reference)
#include <cuda_runtime.h>

#define BB 4
#define SS 4096
#define DD 1024
#define MTOT (BB*SS)

// Scratch (allocation-free: __device__ globals)
__device__ float g_Qx[(size_t)MTOT * DD];
__device__ float g_Kx[(size_t)MTOT * DD];
__device__ float g_Vx[(size_t)MTOT * DD];
__device__ float g_S [(size_t)BB * SS * SS];   // 256 MB scores/probs

// ---------------------------------------------------------------------------
// Kernel 1: projections Y = X @ W for W in {Q,K,V} (F is identity -> dropped)
// 64x64 tile, BK=16, 256 threads, 4x4 micro-tile
// ---------------------------------------------------------------------------
__global__ void proj_kernel(const float* __restrict__ X,
                            const float* __restrict__ Wq,
                            const float* __restrict__ Wk,
                            const float* __restrict__ Wv) {
    const int z = blockIdx.z;
    const float* W = (z == 0) ? Wq : (z == 1) ? Wk : Wv;
    float* Y       = (z == 0) ? g_Qx : (z == 1) ? g_Kx : g_Vx;

    __shared__ float As[64][16];
    __shared__ float Bs[16][64];

    const int tid = threadIdx.x;
    const int m0 = blockIdx.y * 64;
    const int n0 = blockIdx.x * 64;
    const int tx = tid & 15;
    const int ty = tid >> 4;

    float acc[4][4] = {};

    for (int k0 = 0; k0 < DD; k0 += 16) {
        // A tile: 64 rows x 16 cols
        {
            int m = tid >> 2, c = (tid & 3) * 4;
            float4 v = *reinterpret_cast<const float4*>(
                &X[(size_t)(m0 + m) * DD + k0 + c]);
            *reinterpret_cast<float4*>(&As[m][c]) = v;
        }
        // B tile: 16 rows x 64 cols
        {
            int kk = tid >> 4, c = (tid & 15) * 4;
            *reinterpret_cast<float4*>(&Bs[kk][c]) =
                *reinterpret_cast<const float4*>(&W[(size_t)(k0 + kk) * DD + n0 + c]);
        }
        __syncthreads();
#pragma unroll
        for (int kk = 0; kk < 16; kk++) {
            float a[4], b[4];
#pragma unroll
            for (int i = 0; i < 4; i++) a[i] = As[ty * 4 + i][kk];
#pragma unroll
            for (int j = 0; j < 4; j++) b[j] = Bs[kk][tx * 4 + j];
#pragma unroll
            for (int i = 0; i < 4; i++)
#pragma unroll
                for (int j = 0; j < 4; j++) acc[i][j] += a[i] * b[j];
        }
        __syncthreads();
    }

#pragma unroll
    for (int i = 0; i < 4; i++) {
        int m = m0 + ty * 4 + i;
        float4 v = make_float4(acc[i][0], acc[i][1], acc[i][2], acc[i][3]);
        *reinterpret_cast<float4*>(&Y[(size_t)m * DD + n0 + tx * 4]) = v;
    }
}

// ---------------------------------------------------------------------------
// Kernel 2: scores S[b,q,k] = (Qx[b,q,:] . Kx[b,k,:]) / 32, lower-tri tiles only
// ---------------------------------------------------------------------------
__global__ void scores_kernel() {
    const int b  = blockIdx.z;
    const int q0 = blockIdx.y * 64;
    const int k0n = blockIdx.x * 64;
    if (k0n > q0 + 63) return;   // tile fully above the diagonal: skip

    const float* Qp = g_Qx + (size_t)b * SS * DD;
    const float* Kp = g_Kx + (size_t)b * SS * DD;

    __shared__ float As[64][16];
    __shared__ float Bs[16][64];

    const int tid = threadIdx.x;
    const int tx = tid & 15;
    const int ty = tid >> 4;

    float acc[4][4] = {};

    for (int d0 = 0; d0 < DD; d0 += 16) {
        // Q tile
        {
            int m = tid >> 2, c = (tid & 3) * 4;
            float4 v = *reinterpret_cast<const float4*>(
                &Qp[(size_t)(q0 + m) * DD + d0 + c]);
            *reinterpret_cast<float4*>(&As[m][c]) = v;
        }
        // K tile, transposed into Bs[dd][n]
        {
            int r = tid >> 2, c = (tid & 3) * 4;
            float4 v = *reinterpret_cast<const float4*>(
                &Kp[(size_t)(k0n + r) * DD + d0 + c]);
            Bs[c + 0][r] = v.x;
            Bs[c + 1][r] = v.y;
            Bs[c + 2][r] = v.z;
            Bs[c + 3][r] = v.w;
        }
        __syncthreads();
#pragma unroll
        for (int kk = 0; kk < 16; kk++) {
            float a[4], bmat[4];
#pragma unroll
            for (int i = 0; i < 4; i++) a[i] = As[ty * 4 + i][kk];
#pragma unroll
            for (int j = 0; j < 4; j++) bmat[j] = Bs[kk][tx * 4 + j];
#pragma unroll
            for (int i = 0; i < 4; i++)
#pragma unroll
                for (int j = 0; j < 4; j++) acc[i][j] += a[i] * bmat[j];
        }
        __syncthreads();
    }

    float* Sp = g_S + (size_t)b * SS * SS;
    const float scale = 0.03125f;  // 1/sqrt(1024)
#pragma unroll
    for (int i = 0; i < 4; i++) {
        int q = q0 + ty * 4 + i;
        float4 v = make_float4(acc[i][0] * scale, acc[i][1] * scale,
                               acc[i][2] * scale, acc[i][3] * scale);
        *reinterpret_cast<float4*>(&Sp[(size_t)q * SS + k0n + tx * 4]) = v;
    }
}

// ---------------------------------------------------------------------------
// Kernel 3: softmax over valid prefix [0, q] of each row (rest is ignored).
// Whole row cached in SMEM: one global read + one write.
// ---------------------------------------------------------------------------
__global__ void softmax_kernel() {
    const int q = blockIdx.x;
    const int b = blockIdx.y;
    float* row = g_S + (size_t)b * SS * SS + (size_t)q * SS;
    const int len = q + 1;

    __shared__ float buf[SS];
    __shared__ float red[256];
    const int tid = threadIdx.x;

    float mx = -1e30f;
    for (int i = tid; i < len; i += 256) {
        float v = row[i];
        buf[i] = v;
        mx = fmaxf(mx, v);
    }
    red[tid] = mx;
    __syncthreads();
    for (int s = 128; s > 0; s >>= 1) {
        if (tid < s) red[tid] = fmaxf(red[tid], red[tid + s]);
        __syncthreads();
    }
    mx = red[0];
    __syncthreads();

    float sum = 0.f;
    for (int i = tid; i < len; i += 256) {
        float e = __expf(buf[i] - mx);
        buf[i] = e;
        sum += e;
    }
    red[tid] = sum;
    __syncthreads();
    for (int s = 128; s > 0; s >>= 1) {
        if (tid < s) red[tid] += red[tid + s];
        __syncthreads();
    }
    const float inv = 1.0f / red[0];

    for (int i = tid; i < len; i += 256) row[i] = buf[i] * inv;
}

// ---------------------------------------------------------------------------
// Kernel 4: O = P @ Vx with triangular k-loop; mask only on diagonal tiles.
// ---------------------------------------------------------------------------
__global__ void pv_kernel(float* __restrict__ Out) {
    const int b  = blockIdx.z;
    const int q0 = blockIdx.y * 64;
    const int n0 = blockIdx.x * 64;

    const float* P  = g_S  + (size_t)b * SS * SS;
    const float* Vp = g_Vx + (size_t)b * SS * DD;

    __shared__ float As[64][16];
    __shared__ float Bs[16][64];

    const int tid = threadIdx.x;
    const int tx = tid & 15;
    const int ty = tid >> 4;

    float acc[4][4] = {};
    const int kmax = q0 + 64;  // keys strictly <= q < q0+64

    for (int k0 = 0; k0 < kmax; k0 += 16) {
        // P tile with causal mask (garbage above diagonal in g_S -> zero)
        {
            int m = tid >> 2, c = (tid & 3) * 4;
            int q = q0 + m;
            float4 v = *reinterpret_cast<const float4*>(
                &P[(size_t)q * SS + k0 + c]);
            float vals[4] = {v.x, v.y, v.z, v.w};
            if (k0 + 16 > q0) {  // diagonal-region tile: per-element mask
#pragma unroll
                for (int j = 0; j < 4; j++)
                    if (k0 + c + j > q) vals[j] = 0.f;
            }
            As[m][c + 0] = vals[0];
            As[m][c + 1] = vals[1];
            As[m][c + 2] = vals[2];
            As[m][c + 3] = vals[3];
        }
        // V tile
        {
            int kk = tid >> 4, cc = (tid & 15) * 4;
            *reinterpret_cast<float4*>(&Bs[kk][cc]) =
                *reinterpret_cast<const float4*>(&Vp[(size_t)(k0 + kk) * DD + n0 + cc]);
        }
        __syncthreads();
#pragma unroll
        for (int kk = 0; kk < 16; kk++) {
            float a[4], bmat[4];
#pragma unroll
            for (int i = 0; i < 4; i++) a[i] = As[ty * 4 + i][kk];
#pragma unroll
            for (int j = 0; j < 4; j++) bmat[j] = Bs[kk][tx * 4 + j];
#pragma unroll
            for (int i = 0; i < 4; i++)
#pragma unroll
                for (int j = 0; j < 4; j++) acc[i][j] += a[i] * bmat[j];
        }
        __syncthreads();
    }

#pragma unroll
    for (int i = 0; i < 4; i++) {
        int q = q0 + ty * 4 + i;
        float4 v = make_float4(acc[i][0], acc[i][1], acc[i][2], acc[i][3]);
        *reinterpret_cast<float4*>(&Out[(size_t)b * SS * DD + (size_t)q * DD + n0 + tx * 4]) = v;
    }
}

// ---------------------------------------------------------------------------
extern "C" void kernel_launch(void* const* d_in, const int* in_sizes, int n_in,
                              void* d_out, int out_size) {
    const float* x  = (const float*)d_in[0];
    const float* Q  = (const float*)d_in[1];
    const float* K  = (const float*)d_in[2];
    const float* V  = (const float*)d_in[3];
    float* out = (float*)d_out;

    // 1) projections: Qx, Kx, Vx
    {
        dim3 grid(DD / 64, MTOT / 64, 3);
        proj_kernel<<<grid, 256>>>(x, Q, K, V);
    }
    // 2) scores (lower-tri tiles)
    {
        dim3 grid(SS / 64, SS / 64, BB);
        scores_kernel<<<grid, 256>>>();
    }
    // 3) softmax per row
    {
        dim3 grid(SS, BB);
        softmax_kernel<<<grid, 256>>>();
    }
    // 4) O = P @ Vx
    {
        dim3 grid(DD / 64, SS / 64, BB);
        pv_kernel<<<grid, 256>>>(out);
    }
}

// round 4
// speedup vs baseline: 2.5469x; 2.5469x over previous
#include <cuda_runtime.h>
#include <cuda_fp16.h>
#include <cstdint>

#define BB 4
#define SS 4096
#define DD 1024
#define MTOT (BB*SS)

#define BM 128
#define BN 128
#define BK 32
#define PITCH 40                    // halfwords per smem row (32 + 8 pad)
#define TILE_HW (128*PITCH)         // 5120 halfwords per tile
#define STAGE_B (4*TILE_HW*2)       // Ah,Al,Bh,Bl one stage, bytes
#define SMEM_BYTES (2*STAGE_B)      // 81920

// ---------------- device scratch ----------------
__device__ __half g_xh [(size_t)MTOT*DD];
__device__ __half g_xl [(size_t)MTOT*DD];
__device__ __half g_Wth[(size_t)3*DD*DD];   // W^T: [z][n][k]
__device__ __half g_Wtl[(size_t)3*DD*DD];
__device__ __half g_Qxh[(size_t)MTOT*DD];
__device__ __half g_Qxl[(size_t)MTOT*DD];
__device__ __half g_Kxh[(size_t)MTOT*DD];
__device__ __half g_Kxl[(size_t)MTOT*DD];
__device__ float  g_Vx [(size_t)MTOT*DD];
__device__ __half g_Vth[(size_t)MTOT*DD];   // Vx^T: [b][d][s]
__device__ __half g_Vtl[(size_t)MTOT*DD];
__device__ float  g_S  [(size_t)BB*SS*SS];
__device__ __half g_Ph [(size_t)BB*SS*SS];
__device__ __half g_Pl [(size_t)BB*SS*SS];

// ---------------- asm helpers ----------------
__device__ __forceinline__ uint32_t smem_u32(const void* p){
    uint32_t a;
    asm("{ .reg .u64 t; cvta.to.shared.u64 t, %1; cvt.u32.u64 %0, t; }" : "=r"(a) : "l"(p));
    return a;
}
#define CPA(dst, src) asm volatile("cp.async.cg.shared.global [%0], [%1], 16;" :: "r"(dst), "l"(src))
#define CPC() asm volatile("cp.async.commit_group;")
#define CPW() asm volatile("cp.async.wait_group 0;")

#define LDSM4(r0,r1,r2,r3,addr) \
    asm volatile("ldmatrix.sync.aligned.m8n8.x4.shared.b16 {%0,%1,%2,%3}, [%4];" \
        : "=r"(r0), "=r"(r1), "=r"(r2), "=r"(r3) : "r"(addr))

#define MMA(d, a, b) asm volatile( \
    "mma.sync.aligned.m16n8k16.row.col.f32.f16.f16.f32 " \
    "{%0,%1,%2,%3}, {%4,%5,%6,%7}, {%8,%9}, {%0,%1,%2,%3};" \
    : "+f"((d)[0]), "+f"((d)[1]), "+f"((d)[2]), "+f"((d)[3]) \
    : "r"((a)[0]), "r"((a)[1]), "r"((a)[2]), "r"((a)[3]), "r"((b)[0]), "r"((b)[1]))

__device__ __forceinline__ void split2(float v, __half& h, __half& l){
    h = __float2half(v);
    l = __float2half(v - __half2float(h));
}

// ---------------- stage load (cp.async) ----------------
__device__ __forceinline__ void load_stage(uint32_t sm,
    const __half* Ah, const __half* Al, size_t lda, int r0a,
    const __half* Bh, const __half* Bl, size_t ldb, int r0b,
    int k0, int tid)
{
#pragma unroll
    for (int i = 0; i < 2; i++){
        int id = tid + i*256;                 // 0..511
        int r = id >> 2, c = (id & 3) * 8;    // halfword column
        uint32_t so = (uint32_t)(r*PITCH + c) * 2;
        size_t goa = (size_t)(r0a + r)*lda + k0 + c;
        size_t gob = (size_t)(r0b + r)*ldb + k0 + c;
        CPA(sm + so,                 Ah + goa);
        CPA(sm + TILE_HW*2   + so,   Al + goa);
        CPA(sm + TILE_HW*4   + so,   Bh + gob);
        CPA(sm + TILE_HW*6   + so,   Bl + gob);
    }
}

// ---------------- stage compute: 3-pass split mma ----------------
__device__ __forceinline__ void compute_stage(uint32_t sm, int lane, int wm, int wn,
                                              float acc[2][8][4])
{
    const uint32_t aAh = sm;
    const uint32_t aAl = sm + TILE_HW*2;
    const uint32_t aBh = sm + TILE_HW*4;
    const uint32_t aBl = sm + TILE_HW*6;
    const int ar = lane & 15;
    const int ak = (lane >> 4) * 8;
    const int br = (lane & 7) | ((lane >> 4) << 3);
    const int bk = ((lane >> 3) & 1) * 8;
#pragma unroll
    for (int ks = 0; ks < 2; ks++){
        uint32_t ah[2][4], al[2][4], bh[8][2], bl[8][2];
#pragma unroll
        for (int mi = 0; mi < 2; mi++){
            uint32_t off = (uint32_t)((wm*32 + mi*16 + ar)*PITCH + ks*16 + ak) * 2;
            LDSM4(ah[mi][0], ah[mi][1], ah[mi][2], ah[mi][3], aAh + off);
            LDSM4(al[mi][0], al[mi][1], al[mi][2], al[mi][3], aAl + off);
        }
#pragma unroll
        for (int np = 0; np < 4; np++){
            uint32_t off = (uint32_t)((wn*64 + np*16 + br)*PITCH + ks*16 + bk) * 2;
            LDSM4(bh[2*np][0], bh[2*np][1], bh[2*np+1][0], bh[2*np+1][1], aBh + off);
            LDSM4(bl[2*np][0], bl[2*np][1], bl[2*np+1][0], bl[2*np+1][1], aBl + off);
        }
#pragma unroll
        for (int mi = 0; mi < 2; mi++)
#pragma unroll
            for (int ni = 0; ni < 8; ni++){
                MMA(acc[mi][ni], ah[mi], bh[ni]);
                MMA(acc[mi][ni], ah[mi], bl[ni]);
                MMA(acc[mi][ni], al[mi], bh[ni]);
            }
    }
}

// ---------------- full GEMM mainloop (2-stage pipeline) ----------------
__device__ __forceinline__ void gemm_run(uint32_t sm, int tid,
    const __half* Ah, const __half* Al, size_t lda, int r0a,
    const __half* Bh, const __half* Bl, size_t ldb, int r0b,
    int ktiles, float acc[2][8][4])
{
    const int lane = tid & 31, wid = tid >> 5;
    const int wm = wid & 3, wn = wid >> 2;
    load_stage(sm, Ah, Al, lda, r0a, Bh, Bl, ldb, r0b, 0, tid);
    CPC();
    for (int kt = 0; kt < ktiles; kt++){
        CPW();
        __syncthreads();
        if (kt + 1 < ktiles){
            load_stage(sm + ((kt+1)&1)*STAGE_B, Ah, Al, lda, r0a,
                       Bh, Bl, ldb, r0b, (kt+1)*BK, tid);
            CPC();
        }
        compute_stage(sm + (kt&1)*STAGE_B, lane, wm, wn, acc);
        __syncthreads();
    }
}

// ---------------- kernel 1: split x -> fp16 hi/lo ----------------
__global__ void k_split_x(const float* __restrict__ x){
    size_t i = ((size_t)blockIdx.x * 256 + threadIdx.x) * 4;
    float4 v = *reinterpret_cast<const float4*>(x + i);
    __half h[4], l[4];
    split2(v.x, h[0], l[0]); split2(v.y, h[1], l[1]);
    split2(v.z, h[2], l[2]); split2(v.w, h[3], l[3]);
    __half2 h01{h[0],h[1]}, h23{h[2],h[3]}, l01{l[0],l[1]}, l23{l[2],l[3]};
    *reinterpret_cast<__half2*>(g_xh + i)     = h01;
    *reinterpret_cast<__half2*>(g_xh + i + 2) = h23;
    *reinterpret_cast<__half2*>(g_xl + i)     = l01;
    *reinterpret_cast<__half2*>(g_xl + i + 2) = l23;
}

// ---------------- kernel 2: transpose + split weights ----------------
__global__ void k_split_w(const float* __restrict__ Wq,
                          const float* __restrict__ Wk,
                          const float* __restrict__ Wv){
    const int z = blockIdx.z;
    const float* W = (z == 0) ? Wq : (z == 1) ? Wk : Wv;
    __half* H = g_Wth + (size_t)z*DD*DD;
    __half* L = g_Wtl + (size_t)z*DD*DD;
    __shared__ float t[32][33];
    int tx = threadIdx.x, ty = threadIdx.y;
    int kb = blockIdx.y * 32, nb = blockIdx.x * 32;
#pragma unroll
    for (int j = 0; j < 4; j++)
        t[ty + j*8][tx] = W[(size_t)(kb + ty + j*8)*DD + nb + tx];
    __syncthreads();
#pragma unroll
    for (int j = 0; j < 4; j++){
        int n = nb + ty + j*8, k = kb + tx;
        __half h, l;
        split2(t[tx][ty + j*8], h, l);
        H[(size_t)n*DD + k] = h;
        L[(size_t)n*DD + k] = l;
    }
}

// ---------------- kernel 3: projections ----------------
__global__ void __launch_bounds__(256, 1) k_proj(){
    extern __shared__ __align__(16) char smem[];
    uint32_t sm = smem_u32(smem);
    const int tid = threadIdx.x;
    const int z = blockIdx.z, m0 = blockIdx.y*BM, n0 = blockIdx.x*BN;
    float acc[2][8][4] = {};
    gemm_run(sm, tid, g_xh, g_xl, DD, m0,
             g_Wth + (size_t)z*DD*DD, g_Wtl + (size_t)z*DD*DD, DD, n0,
             DD/BK, acc);
    const int lane = tid & 31, wid = tid >> 5, wm = wid & 3, wn = wid >> 2;
    const int r = lane >> 2, c = (lane & 3) * 2;
#pragma unroll
    for (int mi = 0; mi < 2; mi++)
#pragma unroll
        for (int ni = 0; ni < 8; ni++){
            int row = m0 + wm*32 + mi*16 + r;
            int col = n0 + wn*64 + ni*8 + c;
#pragma unroll
            for (int hrow = 0; hrow < 2; hrow++){
                float v0 = acc[mi][ni][hrow*2 + 0];
                float v1 = acc[mi][ni][hrow*2 + 1];
                size_t o = (size_t)(row + hrow*8)*DD + col;
                if (z < 2){
                    __half* H = z ? g_Kxh : g_Qxh;
                    __half* L = z ? g_Kxl : g_Qxl;
                    __half h0,l0,h1,l1;
                    split2(v0, h0, l0); split2(v1, h1, l1);
                    __half2 hp{h0,h1}, lp{l0,l1};
                    *reinterpret_cast<__half2*>(H + o) = hp;
                    *reinterpret_cast<__half2*>(L + o) = lp;
                } else {
                    *reinterpret_cast<float2*>(g_Vx + o) = make_float2(v0, v1);
                }
            }
        }
}

// ---------------- kernel 4: transpose + split Vx ----------------
__global__ void k_vtrans(){
    const int b = blockIdx.z;
    const float* Vx = g_Vx + (size_t)b*SS*DD;
    __half* H = g_Vth + (size_t)b*DD*SS;
    __half* L = g_Vtl + (size_t)b*DD*SS;
    __shared__ float t[32][33];
    int tx = threadIdx.x, ty = threadIdx.y;
    int s0 = blockIdx.y * 32, d0 = blockIdx.x * 32;
#pragma unroll
    for (int j = 0; j < 4; j++)
        t[ty + j*8][tx] = Vx[(size_t)(s0 + ty + j*8)*DD + d0 + tx];
    __syncthreads();
#pragma unroll
    for (int j = 0; j < 4; j++){
        int d = d0 + ty + j*8, s = s0 + tx;
        __half h, l;
        split2(t[tx][ty + j*8], h, l);
        H[(size_t)d*SS + s] = h;
        L[(size_t)d*SS + s] = l;
    }
}

// ---------------- kernel 5: scores (lower-tri tiles) ----------------
__global__ void __launch_bounds__(256, 1) k_scores(){
    const int kt = blockIdx.x, qt = blockIdx.y, b = blockIdx.z;
    if (kt > qt) return;
    extern __shared__ __align__(16) char smem[];
    uint32_t sm = smem_u32(smem);
    const int tid = threadIdx.x;
    float acc[2][8][4] = {};
    gemm_run(sm, tid,
             g_Qxh + (size_t)b*SS*DD, g_Qxl + (size_t)b*SS*DD, DD, qt*BM,
             g_Kxh + (size_t)b*SS*DD, g_Kxl + (size_t)b*SS*DD, DD, kt*BN,
             DD/BK, acc);
    const int lane = tid & 31, wid = tid >> 5, wm = wid & 3, wn = wid >> 2;
    const int r = lane >> 2, c = (lane & 3) * 2;
    float* Sp = g_S + (size_t)b*SS*SS;
#pragma unroll
    for (int mi = 0; mi < 2; mi++)
#pragma unroll
        for (int ni = 0; ni < 8; ni++){
            int row = qt*BM + wm*32 + mi*16 + r;
            int col = kt*BN + wn*64 + ni*8 + c;
#pragma unroll
            for (int hrow = 0; hrow < 2; hrow++){
                size_t o = (size_t)(row + hrow*8)*SS + col;
                *reinterpret_cast<float2*>(Sp + o) =
                    make_float2(acc[mi][ni][hrow*2+0]*0.03125f,
                                acc[mi][ni][hrow*2+1]*0.03125f);
            }
        }
}

// ---------------- kernel 6: softmax -> split fp16 probs + pad ----------------
__global__ void k_softmax(){
    const int q = blockIdx.x;
    const int b = blockIdx.y;
    const float* row = g_S + (size_t)b*SS*SS + (size_t)q*SS;
    __half* Ph = g_Ph + (size_t)b*SS*SS + (size_t)q*SS;
    __half* Pl = g_Pl + (size_t)b*SS*SS + (size_t)q*SS;
    const int len = q + 1;

    __shared__ float buf[SS];
    __shared__ float red[256];
    const int tid = threadIdx.x;

    float mx = -1e30f;
    for (int i = tid; i < len; i += 256){
        float v = row[i];
        buf[i] = v;
        mx = fmaxf(mx, v);
    }
    red[tid] = mx;
    __syncthreads();
    for (int s = 128; s > 0; s >>= 1){
        if (tid < s) red[tid] = fmaxf(red[tid], red[tid + s]);
        __syncthreads();
    }
    mx = red[0];
    __syncthreads();

    float sum = 0.f;
    for (int i = tid; i < len; i += 256){
        float e = __expf(buf[i] - mx);
        buf[i] = e;
        sum += e;
    }
    red[tid] = sum;
    __syncthreads();
    for (int s = 128; s > 0; s >>= 1){
        if (tid < s) red[tid] += red[tid + s];
        __syncthreads();
    }
    const float inv = 1.0f / red[0];
    __syncthreads();

    for (int i = tid; i < len; i += 256){
        __half h, l;
        split2(buf[i] * inv, h, l);
        Ph[i] = h; Pl[i] = l;
    }
    // zero-pad to the 128-tile boundary so PV's diagonal tiles read zeros
    const int bound = ((q >> 7) + 1) << 7;
    const __half z = __float2half(0.f);
    for (int i = len + tid; i < bound; i += 256){ Ph[i] = z; Pl[i] = z; }
}

// ---------------- kernel 7: O = P @ V (triangular K range) ----------------
__global__ void __launch_bounds__(256, 1) k_pv(float* __restrict__ Out){
    const int dt = blockIdx.x, qt = blockIdx.y, b = blockIdx.z;
    extern __shared__ __align__(16) char smem[];
    uint32_t sm = smem_u32(smem);
    const int tid = threadIdx.x;
    float acc[2][8][4] = {};
    const int ktiles = (qt + 1) * (BM / BK);   // keys up to (qt+1)*128
    gemm_run(sm, tid,
             g_Ph  + (size_t)b*SS*SS, g_Pl  + (size_t)b*SS*SS, SS, qt*BM,
             g_Vth + (size_t)b*DD*SS, g_Vtl + (size_t)b*DD*SS, SS, dt*BN,
             ktiles, acc);
    const int lane = tid & 31, wid = tid >> 5, wm = wid & 3, wn = wid >> 2;
    const int r = lane >> 2, c = (lane & 3) * 2;
#pragma unroll
    for (int mi = 0; mi < 2; mi++)
#pragma unroll
        for (int ni = 0; ni < 8; ni++){
            int row = qt*BM + wm*32 + mi*16 + r;
            int col = dt*BN + wn*64 + ni*8 + c;
#pragma unroll
            for (int hrow = 0; hrow < 2; hrow++){
                size_t o = ((size_t)b*SS + row + hrow*8)*DD + col;
                *reinterpret_cast<float2*>(Out + o) =
                    make_float2(acc[mi][ni][hrow*2+0], acc[mi][ni][hrow*2+1]);
            }
        }
}

// ---------------- host ----------------
extern "C" void kernel_launch(void* const* d_in, const int* in_sizes, int n_in,
                              void* d_out, int out_size) {
    const float* x  = (const float*)d_in[0];
    const float* Q  = (const float*)d_in[1];
    const float* K  = (const float*)d_in[2];
    const float* V  = (const float*)d_in[3];
    float* out = (float*)d_out;

    cudaFuncSetAttribute(k_proj,   cudaFuncAttributeMaxDynamicSharedMemorySize, SMEM_BYTES);
    cudaFuncSetAttribute(k_scores, cudaFuncAttributeMaxDynamicSharedMemorySize, SMEM_BYTES);
    cudaFuncSetAttribute(k_pv,     cudaFuncAttributeMaxDynamicSharedMemorySize, SMEM_BYTES);

    k_split_x<<<(unsigned)((size_t)MTOT*DD/1024), 256>>>(x);
    k_split_w<<<dim3(DD/32, DD/32, 3), dim3(32, 8)>>>(Q, K, V);
    k_proj<<<dim3(DD/BN, MTOT/BM, 3), 256, SMEM_BYTES>>>();
    k_vtrans<<<dim3(DD/32, SS/32, BB), dim3(32, 8)>>>();
    k_scores<<<dim3(SS/BN, SS/BM, BB), 256, SMEM_BYTES>>>();
    k_softmax<<<dim3(SS, BB), 256>>>();
    k_pv<<<dim3(DD/BN, SS/BM, BB), 256, SMEM_BYTES>>>(out);
}

// round 5
// speedup vs baseline: 2.8489x; 1.1186x over previous
#include <cuda_runtime.h>
#include <cuda_fp16.h>
#include <cstdint>

#define BB 4
#define SS 4096
#define DD 1024
#define MTOT (BB*SS)

#define BM 128
#define BN 128
#define BK 32
#define TILE_B (128*64)             // 128 rows x 64 bytes (32 halfwords), swizzled
#define STAGE_B (4*TILE_B)          // Ah,Al,Bh,Bl per stage = 32 KB
#define NSTAGE 3
#define SMEM_BYTES (NSTAGE*STAGE_B) // 96 KB

// ---------------- device scratch ----------------
__device__ __half g_xh [(size_t)MTOT*DD];
__device__ __half g_xl [(size_t)MTOT*DD];
__device__ __half g_Wth[(size_t)3*DD*DD];   // W^T: [z][n][k]
__device__ __half g_Wtl[(size_t)3*DD*DD];
__device__ __half g_Qxh[(size_t)MTOT*DD];
__device__ __half g_Qxl[(size_t)MTOT*DD];
__device__ __half g_Kxh[(size_t)MTOT*DD];
__device__ __half g_Kxl[(size_t)MTOT*DD];
__device__ float  g_Vx [(size_t)MTOT*DD];
__device__ __half g_Vth[(size_t)MTOT*DD];   // Vx^T: [b][d][s]
__device__ __half g_Vtl[(size_t)MTOT*DD];
__device__ float  g_S  [(size_t)BB*SS*SS];
__device__ __half g_Ph [(size_t)BB*SS*SS];
__device__ __half g_Pl [(size_t)BB*SS*SS];

// ---------------- asm helpers ----------------
__device__ __forceinline__ uint32_t smem_u32(const void* p){
    uint32_t a;
    asm("{ .reg .u64 t; cvta.to.shared.u64 t, %1; cvt.u32.u64 %0, t; }" : "=r"(a) : "l"(p));
    return a;
}
#define CPA(dst, src) asm volatile("cp.async.cg.shared.global [%0], [%1], 16;" :: "r"(dst), "l"(src))
#define CPC()  asm volatile("cp.async.commit_group;")
#define CPW1() asm volatile("cp.async.wait_group 1;")

#define LDSM4(r0,r1,r2,r3,addr) \
    asm volatile("ldmatrix.sync.aligned.m8n8.x4.shared.b16 {%0,%1,%2,%3}, [%4];" \
        : "=r"(r0), "=r"(r1), "=r"(r2), "=r"(r3) : "r"(addr))

#define MMA(d, a, b) asm volatile( \
    "mma.sync.aligned.m16n8k16.row.col.f32.f16.f16.f32 " \
    "{%0,%1,%2,%3}, {%4,%5,%6,%7}, {%8,%9}, {%0,%1,%2,%3};" \
    : "+f"((d)[0]), "+f"((d)[1]), "+f"((d)[2]), "+f"((d)[3]) \
    : "r"((a)[0]), "r"((a)[1]), "r"((a)[2]), "r"((a)[3]), "r"((b)[0]), "r"((b)[1]))

__device__ __forceinline__ void split2(float v, __half& h, __half& l){
    h = __float2half(v);
    l = __float2half(v - __half2float(h));
}

// swizzled byte offset within a tile: row r (0..127), 16B chunk c (0..3)
__device__ __forceinline__ uint32_t swz(uint32_t r, uint32_t c){
    return r*64u + ((c ^ (r & 3u)) * 16u);
}

// ---------------- stage load (cp.async, swizzled) ----------------
__device__ __forceinline__ void load_stage(uint32_t sm,
    const __half* Ah, const __half* Al, size_t lda, int r0a,
    const __half* Bh, const __half* Bl, size_t ldb, int r0b,
    int k0, int tid)
{
#pragma unroll
    for (int i = 0; i < 2; i++){
        int id = tid + i*256;                 // 0..511
        uint32_t r = (uint32_t)(id >> 2), c = (uint32_t)(id & 3);
        uint32_t so = swz(r, c);
        size_t goa = (size_t)(r0a + (int)r)*lda + k0 + c*8;
        size_t gob = (size_t)(r0b + (int)r)*ldb + k0 + c*8;
        CPA(sm + so,            Ah + goa);
        CPA(sm + TILE_B   + so, Al + goa);
        CPA(sm + TILE_B*2 + so, Bh + gob);
        CPA(sm + TILE_B*3 + so, Bl + gob);
    }
}

// ---------------- stage compute: 3-pass split mma ----------------
__device__ __forceinline__ void compute_stage(uint32_t sm, int lane, int wm, int wn,
                                              float acc[2][8][4])
{
    const uint32_t aAh = sm;
    const uint32_t aAl = sm + TILE_B;
    const uint32_t aBh = sm + TILE_B*2;
    const uint32_t aBl = sm + TILE_B*3;
    const int ar = lane & 15;
    const int ac = lane >> 4;               // A chunk sub-index (0/1)
    const int br = (lane & 7) | ((lane >> 4) << 3);
    const int bc = (lane >> 3) & 1;         // B chunk sub-index (0/1)
#pragma unroll
    for (int ks = 0; ks < 2; ks++){
        uint32_t ah[2][4], al[2][4], bh[8][2], bl[8][2];
#pragma unroll
        for (int mi = 0; mi < 2; mi++){
            uint32_t r = (uint32_t)(wm*32 + mi*16 + ar);
            uint32_t off = swz(r, (uint32_t)(ks*2 + ac));
            LDSM4(ah[mi][0], ah[mi][1], ah[mi][2], ah[mi][3], aAh + off);
            LDSM4(al[mi][0], al[mi][1], al[mi][2], al[mi][3], aAl + off);
        }
#pragma unroll
        for (int np = 0; np < 4; np++){
            uint32_t r = (uint32_t)(wn*64 + np*16 + br);
            uint32_t off = swz(r, (uint32_t)(ks*2 + bc));
            LDSM4(bh[2*np][0], bh[2*np][1], bh[2*np+1][0], bh[2*np+1][1], aBh + off);
            LDSM4(bl[2*np][0], bl[2*np][1], bl[2*np+1][0], bl[2*np+1][1], aBl + off);
        }
#pragma unroll
        for (int mi = 0; mi < 2; mi++)
#pragma unroll
            for (int ni = 0; ni < 8; ni++){
                MMA(acc[mi][ni], ah[mi], bh[ni]);
                MMA(acc[mi][ni], ah[mi], bl[ni]);
                MMA(acc[mi][ni], al[mi], bh[ni]);
            }
    }
}

// ---------------- full GEMM mainloop (3-stage pipeline, 1 sync/iter) ----------------
__device__ __forceinline__ void gemm_run(uint32_t sm, int tid,
    const __half* Ah, const __half* Al, size_t lda, int r0a,
    const __half* Bh, const __half* Bl, size_t ldb, int r0b,
    int ktiles, float acc[2][8][4])
{
    const int lane = tid & 31, wid = tid >> 5;
    const int wm = wid & 3, wn = wid >> 2;
    const int kend = ktiles * BK;

    // prologue: prefetch stages 0 and 1
    load_stage(sm, Ah, Al, lda, r0a, Bh, Bl, ldb, r0b, 0, tid);
    CPC();
    {
        int k1 = min(BK, kend - BK);
        load_stage(sm + STAGE_B, Ah, Al, lda, r0a, Bh, Bl, ldb, r0b, k1, tid);
        CPC();
    }

    int buf = 0;
    int nxt = 2 % NSTAGE;
    for (int kt = 0; kt < ktiles; kt++){
        CPW1();                 // stage kt complete (<=1 group pending)
        __syncthreads();        // also guards overwrite of buffer (kt-1)%3 below
        {
            int k2 = min((kt + 2) * BK, kend - BK);   // clamped prefetch
            load_stage(sm + nxt*STAGE_B, Ah, Al, lda, r0a, Bh, Bl, ldb, r0b, k2, tid);
            CPC();
        }
        compute_stage(sm + buf*STAGE_B, lane, wm, wn, acc);
        buf = (buf + 1 == NSTAGE) ? 0 : buf + 1;
        nxt = (nxt + 1 == NSTAGE) ? 0 : nxt + 1;
    }
}

// ---------------- kernel 1: split x -> fp16 hi/lo ----------------
__global__ void k_split_x(const float* __restrict__ x){
    size_t i = ((size_t)blockIdx.x * 256 + threadIdx.x) * 4;
    float4 v = *reinterpret_cast<const float4*>(x + i);
    __half h[4], l[4];
    split2(v.x, h[0], l[0]); split2(v.y, h[1], l[1]);
    split2(v.z, h[2], l[2]); split2(v.w, h[3], l[3]);
    __half2 h01{h[0],h[1]}, h23{h[2],h[3]}, l01{l[0],l[1]}, l23{l[2],l[3]};
    *reinterpret_cast<__half2*>(g_xh + i)     = h01;
    *reinterpret_cast<__half2*>(g_xh + i + 2) = h23;
    *reinterpret_cast<__half2*>(g_xl + i)     = l01;
    *reinterpret_cast<__half2*>(g_xl + i + 2) = l23;
}

// ---------------- kernel 2: transpose + split weights ----------------
__global__ void k_split_w(const float* __restrict__ Wq,
                          const float* __restrict__ Wk,
                          const float* __restrict__ Wv){
    const int z = blockIdx.z;
    const float* W = (z == 0) ? Wq : (z == 1) ? Wk : Wv;
    __half* H = g_Wth + (size_t)z*DD*DD;
    __half* L = g_Wtl + (size_t)z*DD*DD;
    __shared__ float t[32][33];
    int tx = threadIdx.x, ty = threadIdx.y;
    int kb = blockIdx.y * 32, nb = blockIdx.x * 32;
#pragma unroll
    for (int j = 0; j < 4; j++)
        t[ty + j*8][tx] = W[(size_t)(kb + ty + j*8)*DD + nb + tx];
    __syncthreads();
#pragma unroll
    for (int j = 0; j < 4; j++){
        int n = nb + ty + j*8, k = kb + tx;
        __half h, l;
        split2(t[tx][ty + j*8], h, l);
        H[(size_t)n*DD + k] = h;
        L[(size_t)n*DD + k] = l;
    }
}

// ---------------- kernel 3: projections ----------------
__global__ void __launch_bounds__(256, 1) k_proj(){
    extern __shared__ __align__(128) char smem[];
    uint32_t sm = smem_u32(smem);
    const int tid = threadIdx.x;
    const int z = blockIdx.z, m0 = blockIdx.y*BM, n0 = blockIdx.x*BN;
    float acc[2][8][4] = {};
    gemm_run(sm, tid, g_xh, g_xl, DD, m0,
             g_Wth + (size_t)z*DD*DD, g_Wtl + (size_t)z*DD*DD, DD, n0,
             DD/BK, acc);
    const int lane = tid & 31, wid = tid >> 5, wm = wid & 3, wn = wid >> 2;
    const int r = lane >> 2, c = (lane & 3) * 2;
#pragma unroll
    for (int mi = 0; mi < 2; mi++)
#pragma unroll
        for (int ni = 0; ni < 8; ni++){
            int row = m0 + wm*32 + mi*16 + r;
            int col = n0 + wn*64 + ni*8 + c;
#pragma unroll
            for (int hrow = 0; hrow < 2; hrow++){
                float v0 = acc[mi][ni][hrow*2 + 0];
                float v1 = acc[mi][ni][hrow*2 + 1];
                size_t o = (size_t)(row + hrow*8)*DD + col;
                if (z < 2){
                    __half* H = z ? g_Kxh : g_Qxh;
                    __half* L = z ? g_Kxl : g_Qxl;
                    __half h0,l0,h1,l1;
                    split2(v0, h0, l0); split2(v1, h1, l1);
                    __half2 hp{h0,h1}, lp{l0,l1};
                    *reinterpret_cast<__half2*>(H + o) = hp;
                    *reinterpret_cast<__half2*>(L + o) = lp;
                } else {
                    *reinterpret_cast<float2*>(g_Vx + o) = make_float2(v0, v1);
                }
            }
        }
}

// ---------------- kernel 4: transpose + split Vx ----------------
__global__ void k_vtrans(){
    const int b = blockIdx.z;
    const float* Vx = g_Vx + (size_t)b*SS*DD;
    __half* H = g_Vth + (size_t)b*DD*SS;
    __half* L = g_Vtl + (size_t)b*DD*SS;
    __shared__ float t[32][33];
    int tx = threadIdx.x, ty = threadIdx.y;
    int s0 = blockIdx.y * 32, d0 = blockIdx.x * 32;
#pragma unroll
    for (int j = 0; j < 4; j++)
        t[ty + j*8][tx] = Vx[(size_t)(s0 + ty + j*8)*DD + d0 + tx];
    __syncthreads();
#pragma unroll
    for (int j = 0; j < 4; j++){
        int d = d0 + ty + j*8, s = s0 + tx;
        __half h, l;
        split2(t[tx][ty + j*8], h, l);
        H[(size_t)d*SS + s] = h;
        L[(size_t)d*SS + s] = l;
    }
}

// ---------------- kernel 5: scores (lower-tri tiles) ----------------
__global__ void __launch_bounds__(256, 1) k_scores(){
    const int kt = blockIdx.x, qt = blockIdx.y, b = blockIdx.z;
    if (kt > qt) return;
    extern __shared__ __align__(128) char smem[];
    uint32_t sm = smem_u32(smem);
    const int tid = threadIdx.x;
    float acc[2][8][4] = {};
    gemm_run(sm, tid,
             g_Qxh + (size_t)b*SS*DD, g_Qxl + (size_t)b*SS*DD, DD, qt*BM,
             g_Kxh + (size_t)b*SS*DD, g_Kxl + (size_t)b*SS*DD, DD, kt*BN,
             DD/BK, acc);
    const int lane = tid & 31, wid = tid >> 5, wm = wid & 3, wn = wid >> 2;
    const int r = lane >> 2, c = (lane & 3) * 2;
    float* Sp = g_S + (size_t)b*SS*SS;
#pragma unroll
    for (int mi = 0; mi < 2; mi++)
#pragma unroll
        for (int ni = 0; ni < 8; ni++){
            int row = qt*BM + wm*32 + mi*16 + r;
            int col = kt*BN + wn*64 + ni*8 + c;
#pragma unroll
            for (int hrow = 0; hrow < 2; hrow++){
                size_t o = (size_t)(row + hrow*8)*SS + col;
                *reinterpret_cast<float2*>(Sp + o) =
                    make_float2(acc[mi][ni][hrow*2+0]*0.03125f,
                                acc[mi][ni][hrow*2+1]*0.03125f);
            }
        }
}

// ---------------- kernel 6: softmax -> split fp16 probs + pad ----------------
__global__ void k_softmax(){
    const int q = blockIdx.x;
    const int b = blockIdx.y;
    const float* row = g_S + (size_t)b*SS*SS + (size_t)q*SS;
    __half* Ph = g_Ph + (size_t)b*SS*SS + (size_t)q*SS;
    __half* Pl = g_Pl + (size_t)b*SS*SS + (size_t)q*SS;
    const int len = q + 1;

    __shared__ float buf[SS];
    __shared__ float red[256];
    const int tid = threadIdx.x;

    float mx = -1e30f;
    for (int i = tid; i < len; i += 256){
        float v = row[i];
        buf[i] = v;
        mx = fmaxf(mx, v);
    }
    red[tid] = mx;
    __syncthreads();
    for (int s = 128; s > 0; s >>= 1){
        if (tid < s) red[tid] = fmaxf(red[tid], red[tid + s]);
        __syncthreads();
    }
    mx = red[0];
    __syncthreads();

    float sum = 0.f;
    for (int i = tid; i < len; i += 256){
        float e = __expf(buf[i] - mx);
        buf[i] = e;
        sum += e;
    }
    red[tid] = sum;
    __syncthreads();
    for (int s = 128; s > 0; s >>= 1){
        if (tid < s) red[tid] += red[tid + s];
        __syncthreads();
    }
    const float inv = 1.0f / red[0];
    __syncthreads();

    for (int i = tid; i < len; i += 256){
        __half h, l;
        split2(buf[i] * inv, h, l);
        Ph[i] = h; Pl[i] = l;
    }
    // zero-pad to the 128-tile boundary so PV's diagonal tiles read zeros
    const int bound = ((q >> 7) + 1) << 7;
    const __half z = __float2half(0.f);
    for (int i = len + tid; i < bound; i += 256){ Ph[i] = z; Pl[i] = z; }
}

// ---------------- kernel 7: O = P @ V (triangular K range) ----------------
__global__ void __launch_bounds__(256, 1) k_pv(float* __restrict__ Out){
    const int dt = blockIdx.x, qt = blockIdx.y, b = blockIdx.z;
    extern __shared__ __align__(128) char smem[];
    uint32_t sm = smem_u32(smem);
    const int tid = threadIdx.x;
    float acc[2][8][4] = {};
    const int ktiles = (qt + 1) * (BM / BK);   // keys up to (qt+1)*128
    gemm_run(sm, tid,
             g_Ph  + (size_t)b*SS*SS, g_Pl  + (size_t)b*SS*SS, SS, qt*BM,
             g_Vth + (size_t)b*DD*SS, g_Vtl + (size_t)b*DD*SS, SS, dt*BN,
             ktiles, acc);
    const int lane = tid & 31, wid = tid >> 5, wm = wid & 3, wn = wid >> 2;
    const int r = lane >> 2, c = (lane & 3) * 2;
#pragma unroll
    for (int mi = 0; mi < 2; mi++)
#pragma unroll
        for (int ni = 0; ni < 8; ni++){
            int row = qt*BM + wm*32 + mi*16 + r;
            int col = dt*BN + wn*64 + ni*8 + c;
#pragma unroll
            for (int hrow = 0; hrow < 2; hrow++){
                size_t o = ((size_t)b*SS + row + hrow*8)*DD + col;
                *reinterpret_cast<float2*>(Out + o) =
                    make_float2(acc[mi][ni][hrow*2+0], acc[mi][ni][hrow*2+1]);
            }
        }
}

// ---------------- host ----------------
extern "C" void kernel_launch(void* const* d_in, const int* in_sizes, int n_in,
                              void* d_out, int out_size) {
    const float* x  = (const float*)d_in[0];
    const float* Q  = (const float*)d_in[1];
    const float* K  = (const float*)d_in[2];
    const float* V  = (const float*)d_in[3];
    float* out = (float*)d_out;

    cudaFuncSetAttribute(k_proj,   cudaFuncAttributeMaxDynamicSharedMemorySize, SMEM_BYTES);
    cudaFuncSetAttribute(k_scores, cudaFuncAttributeMaxDynamicSharedMemorySize, SMEM_BYTES);
    cudaFuncSetAttribute(k_pv,     cudaFuncAttributeMaxDynamicSharedMemorySize, SMEM_BYTES);

    k_split_x<<<(unsigned)((size_t)MTOT*DD/1024), 256>>>(x);
    k_split_w<<<dim3(DD/32, DD/32, 3), dim3(32, 8)>>>(Q, K, V);
    k_proj<<<dim3(DD/BN, MTOT/BM, 3), 256, SMEM_BYTES>>>();
    k_vtrans<<<dim3(DD/32, SS/32, BB), dim3(32, 8)>>>();
    k_scores<<<dim3(SS/BN, SS/BM, BB), 256, SMEM_BYTES>>>();
    k_softmax<<<dim3(SS, BB), 256>>>();
    k_pv<<<dim3(DD/BN, SS/BM, BB), 256, SMEM_BYTES>>>(out);
}

// round 6
// speedup vs baseline: 3.8543x; 1.3529x over previous
#include <cuda_runtime.h>
#include <cuda_fp16.h>
#include <cstdint>

#define BB 4
#define SS 4096
#define DD 1024
#define MTOT (BB*SS)

#define BM 128
#define BN 128
#define BK 32
#define TILE_B (128*64)             // 128 rows x 64 bytes (32 halfwords), swizzled
#define STAGE_B (3*TILE_B)          // Ah, Al, Bh per stage = 24 KB
#define NSTAGE 4
#define SMEM_BYTES (NSTAGE*STAGE_B) // 96 KB

// ---------------- device scratch ----------------
__device__ __half g_xh [(size_t)MTOT*DD];
__device__ __half g_xl [(size_t)MTOT*DD];
__device__ __half g_Wth[(size_t)3*DD*DD];   // W^T hi: [z][n][k]
__device__ __half g_Qxh[(size_t)MTOT*DD];
__device__ __half g_Qxl[(size_t)MTOT*DD];
__device__ __half g_Kxh[(size_t)MTOT*DD];
__device__ float  g_Vx [(size_t)MTOT*DD];
__device__ __half g_Vth[(size_t)MTOT*DD];   // Vx^T hi: [b][d][s]
__device__ float  g_S  [(size_t)BB*SS*SS];
__device__ __half g_Ph [(size_t)BB*SS*SS];
__device__ __half g_Pl [(size_t)BB*SS*SS];

// ---------------- asm helpers ----------------
__device__ __forceinline__ uint32_t smem_u32(const void* p){
    uint32_t a;
    asm("{ .reg .u64 t; cvta.to.shared.u64 t, %1; cvt.u32.u64 %0, t; }" : "=r"(a) : "l"(p));
    return a;
}
#define CPA(dst, src) asm volatile("cp.async.cg.shared.global [%0], [%1], 16;" :: "r"(dst), "l"(src))
#define CPC()  asm volatile("cp.async.commit_group;")
#define CPW2() asm volatile("cp.async.wait_group 2;")

#define LDSM4(r0,r1,r2,r3,addr) \
    asm volatile("ldmatrix.sync.aligned.m8n8.x4.shared.b16 {%0,%1,%2,%3}, [%4];" \
        : "=r"(r0), "=r"(r1), "=r"(r2), "=r"(r3) : "r"(addr))

#define MMA(d, a, b) asm volatile( \
    "mma.sync.aligned.m16n8k16.row.col.f32.f16.f16.f32 " \
    "{%0,%1,%2,%3}, {%4,%5,%6,%7}, {%8,%9}, {%0,%1,%2,%3};" \
    : "+f"((d)[0]), "+f"((d)[1]), "+f"((d)[2]), "+f"((d)[3]) \
    : "r"((a)[0]), "r"((a)[1]), "r"((a)[2]), "r"((a)[3]), "r"((b)[0]), "r"((b)[1]))

__device__ __forceinline__ void split2(float v, __half& h, __half& l){
    h = __float2half(v);
    l = __float2half(v - __half2float(h));
}

// swizzled byte offset within a tile: row r (0..127), 16B chunk c (0..3)
__device__ __forceinline__ uint32_t swz(uint32_t r, uint32_t c){
    return r*64u + ((c ^ (r & 3u)) * 16u);
}

// ---------------- stage load (cp.async, swizzled): Ah, Al, Bh ----------------
__device__ __forceinline__ void load_stage(uint32_t sm,
    const __half* Ah, const __half* Al, size_t lda, int r0a,
    const __half* Bh, size_t ldb, int r0b,
    int k0, int tid)
{
#pragma unroll
    for (int i = 0; i < 2; i++){
        int id = tid + i*256;                 // 0..511
        uint32_t r = (uint32_t)(id >> 2), c = (uint32_t)(id & 3);
        uint32_t so = swz(r, c);
        size_t goa = (size_t)(r0a + (int)r)*lda + k0 + c*8;
        size_t gob = (size_t)(r0b + (int)r)*ldb + k0 + c*8;
        CPA(sm + so,            Ah + goa);
        CPA(sm + TILE_B   + so, Al + goa);
        CPA(sm + TILE_B*2 + so, Bh + gob);
    }
}

// ---------------- stage compute: 2-pass split mma ----------------
__device__ __forceinline__ void compute_stage(uint32_t sm, int lane, int wm, int wn,
                                              float acc[2][8][4])
{
    const uint32_t aAh = sm;
    const uint32_t aAl = sm + TILE_B;
    const uint32_t aBh = sm + TILE_B*2;
    const int ar = lane & 15;
    const int ac = lane >> 4;               // A chunk sub-index (0/1)
    const int br = (lane & 7) | ((lane >> 4) << 3);
    const int bc = (lane >> 3) & 1;         // B chunk sub-index (0/1)
#pragma unroll
    for (int ks = 0; ks < 2; ks++){
        uint32_t ah[2][4], al[2][4], bh[8][2];
#pragma unroll
        for (int mi = 0; mi < 2; mi++){
            uint32_t r = (uint32_t)(wm*32 + mi*16 + ar);
            uint32_t off = swz(r, (uint32_t)(ks*2 + ac));
            LDSM4(ah[mi][0], ah[mi][1], ah[mi][2], ah[mi][3], aAh + off);
            LDSM4(al[mi][0], al[mi][1], al[mi][2], al[mi][3], aAl + off);
        }
#pragma unroll
        for (int np = 0; np < 4; np++){
            uint32_t r = (uint32_t)(wn*64 + np*16 + br);
            uint32_t off = swz(r, (uint32_t)(ks*2 + bc));
            LDSM4(bh[2*np][0], bh[2*np][1], bh[2*np+1][0], bh[2*np+1][1], aBh + off);
        }
#pragma unroll
        for (int mi = 0; mi < 2; mi++)
#pragma unroll
            for (int ni = 0; ni < 8; ni++){
                MMA(acc[mi][ni], ah[mi], bh[ni]);
                MMA(acc[mi][ni], al[mi], bh[ni]);
            }
    }
}

// ---------------- full GEMM mainloop (4-stage pipeline, 1 sync/iter) ----------------
__device__ __forceinline__ void gemm_run(uint32_t sm, int tid,
    const __half* Ah, const __half* Al, size_t lda, int r0a,
    const __half* Bh, size_t ldb, int r0b,
    int ktiles, float acc[2][8][4])
{
    const int lane = tid & 31, wid = tid >> 5;
    const int wm = wid & 3, wn = wid >> 2;
    const int kend = ktiles * BK;

    // prologue: prefetch stages 0,1,2
#pragma unroll
    for (int s = 0; s < NSTAGE - 1; s++){
        int k = min(s * BK, kend - BK);
        load_stage(sm + s*STAGE_B, Ah, Al, lda, r0a, Bh, ldb, r0b, k, tid);
        CPC();
    }

    int buf = 0;
    int nxt = NSTAGE - 1;
    for (int kt = 0; kt < ktiles; kt++){
        CPW2();                 // stage kt complete (<=2 groups pending)
        __syncthreads();        // buffer nxt free: compute(kt-1) done by all warps
        {
            int k = min((kt + NSTAGE - 1) * BK, kend - BK);   // clamped prefetch
            load_stage(sm + nxt*STAGE_B, Ah, Al, lda, r0a, Bh, ldb, r0b, k, tid);
            CPC();
        }
        compute_stage(sm + buf*STAGE_B, lane, wm, wn, acc);
        buf = (buf + 1 == NSTAGE) ? 0 : buf + 1;
        nxt = (nxt + 1 == NSTAGE) ? 0 : nxt + 1;
    }
}

// ---------------- kernel 1: split x -> fp16 hi/lo ----------------
__global__ void k_split_x(const float* __restrict__ x){
    size_t i = ((size_t)blockIdx.x * 256 + threadIdx.x) * 4;
    float4 v = *reinterpret_cast<const float4*>(x + i);
    __half h[4], l[4];
    split2(v.x, h[0], l[0]); split2(v.y, h[1], l[1]);
    split2(v.z, h[2], l[2]); split2(v.w, h[3], l[3]);
    __half2 h01{h[0],h[1]}, h23{h[2],h[3]}, l01{l[0],l[1]}, l23{l[2],l[3]};
    *reinterpret_cast<__half2*>(g_xh + i)     = h01;
    *reinterpret_cast<__half2*>(g_xh + i + 2) = h23;
    *reinterpret_cast<__half2*>(g_xl + i)     = l01;
    *reinterpret_cast<__half2*>(g_xl + i + 2) = l23;
}

// ---------------- kernel 2: transpose weights (hi only) ----------------
__global__ void k_split_w(const float* __restrict__ Wq,
                          const float* __restrict__ Wk,
                          const float* __restrict__ Wv){
    const int z = blockIdx.z;
    const float* W = (z == 0) ? Wq : (z == 1) ? Wk : Wv;
    __half* H = g_Wth + (size_t)z*DD*DD;
    __shared__ float t[32][33];
    int tx = threadIdx.x, ty = threadIdx.y;
    int kb = blockIdx.y * 32, nb = blockIdx.x * 32;
#pragma unroll
    for (int j = 0; j < 4; j++)
        t[ty + j*8][tx] = W[(size_t)(kb + ty + j*8)*DD + nb + tx];
    __syncthreads();
#pragma unroll
    for (int j = 0; j < 4; j++){
        int n = nb + ty + j*8, k = kb + tx;
        H[(size_t)n*DD + k] = __float2half(t[tx][ty + j*8]);
    }
}

// ---------------- kernel 3: projections ----------------
__global__ void __launch_bounds__(256, 1) k_proj(){
    extern __shared__ __align__(128) char smem[];
    uint32_t sm = smem_u32(smem);
    const int tid = threadIdx.x;
    const int z = blockIdx.z, m0 = blockIdx.y*BM, n0 = blockIdx.x*BN;
    float acc[2][8][4] = {};
    gemm_run(sm, tid, g_xh, g_xl, DD, m0,
             g_Wth + (size_t)z*DD*DD, DD, n0, DD/BK, acc);
    const int lane = tid & 31, wid = tid >> 5, wm = wid & 3, wn = wid >> 2;
    const int r = lane >> 2, c = (lane & 3) * 2;
#pragma unroll
    for (int mi = 0; mi < 2; mi++)
#pragma unroll
        for (int ni = 0; ni < 8; ni++){
            int row = m0 + wm*32 + mi*16 + r;
            int col = n0 + wn*64 + ni*8 + c;
#pragma unroll
            for (int hrow = 0; hrow < 2; hrow++){
                float v0 = acc[mi][ni][hrow*2 + 0];
                float v1 = acc[mi][ni][hrow*2 + 1];
                size_t o = (size_t)(row + hrow*8)*DD + col;
                if (z == 0){
                    __half h0,l0,h1,l1;
                    split2(v0, h0, l0); split2(v1, h1, l1);
                    __half2 hp{h0,h1}, lp{l0,l1};
                    *reinterpret_cast<__half2*>(g_Qxh + o) = hp;
                    *reinterpret_cast<__half2*>(g_Qxl + o) = lp;
                } else if (z == 1){
                    __half2 hp{__float2half(v0), __float2half(v1)};
                    *reinterpret_cast<__half2*>(g_Kxh + o) = hp;
                } else {
                    *reinterpret_cast<float2*>(g_Vx + o) = make_float2(v0, v1);
                }
            }
        }
}

// ---------------- kernel 4: transpose Vx (hi only) ----------------
__global__ void k_vtrans(){
    const int b = blockIdx.z;
    const float* Vx = g_Vx + (size_t)b*SS*DD;
    __half* H = g_Vth + (size_t)b*DD*SS;
    __shared__ float t[32][33];
    int tx = threadIdx.x, ty = threadIdx.y;
    int s0 = blockIdx.y * 32, d0 = blockIdx.x * 32;
#pragma unroll
    for (int j = 0; j < 4; j++)
        t[ty + j*8][tx] = Vx[(size_t)(s0 + ty + j*8)*DD + d0 + tx];
    __syncthreads();
#pragma unroll
    for (int j = 0; j < 4; j++){
        int d = d0 + ty + j*8, s = s0 + tx;
        H[(size_t)d*SS + s] = __float2half(t[tx][ty + j*8]);
    }
}

// ---------------- kernel 5: scores (lower-tri tiles) ----------------
__global__ void __launch_bounds__(256, 1) k_scores(){
    const int kt = blockIdx.x, qt = blockIdx.y, b = blockIdx.z;
    if (kt > qt) return;
    extern __shared__ __align__(128) char smem[];
    uint32_t sm = smem_u32(smem);
    const int tid = threadIdx.x;
    float acc[2][8][4] = {};
    gemm_run(sm, tid,
             g_Qxh + (size_t)b*SS*DD, g_Qxl + (size_t)b*SS*DD, DD, qt*BM,
             g_Kxh + (size_t)b*SS*DD, DD, kt*BN, DD/BK, acc);
    const int lane = tid & 31, wid = tid >> 5, wm = wid & 3, wn = wid >> 2;
    const int r = lane >> 2, c = (lane & 3) * 2;
    float* Sp = g_S + (size_t)b*SS*SS;
#pragma unroll
    for (int mi = 0; mi < 2; mi++)
#pragma unroll
        for (int ni = 0; ni < 8; ni++){
            int row = qt*BM + wm*32 + mi*16 + r;
            int col = kt*BN + wn*64 + ni*8 + c;
#pragma unroll
            for (int hrow = 0; hrow < 2; hrow++){
                size_t o = (size_t)(row + hrow*8)*SS + col;
                *reinterpret_cast<float2*>(Sp + o) =
                    make_float2(acc[mi][ni][hrow*2+0]*0.03125f,
                                acc[mi][ni][hrow*2+1]*0.03125f);
            }
        }
}

// ---------------- kernel 6: softmax -> split fp16 probs + pad ----------------
__global__ void k_softmax(){
    const int q = blockIdx.x;
    const int b = blockIdx.y;
    const float* row = g_S + (size_t)b*SS*SS + (size_t)q*SS;
    __half* Ph = g_Ph + (size_t)b*SS*SS + (size_t)q*SS;
    __half* Pl = g_Pl + (size_t)b*SS*SS + (size_t)q*SS;
    const int len = q + 1;

    __shared__ float buf[SS];
    __shared__ float red[256];
    const int tid = threadIdx.x;

    float mx = -1e30f;
    for (int i = tid; i < len; i += 256){
        float v = row[i];
        buf[i] = v;
        mx = fmaxf(mx, v);
    }
    red[tid] = mx;
    __syncthreads();
    for (int s = 128; s > 0; s >>= 1){
        if (tid < s) red[tid] = fmaxf(red[tid], red[tid + s]);
        __syncthreads();
    }
    mx = red[0];
    __syncthreads();

    float sum = 0.f;
    for (int i = tid; i < len; i += 256){
        float e = __expf(buf[i] - mx);
        buf[i] = e;
        sum += e;
    }
    red[tid] = sum;
    __syncthreads();
    for (int s = 128; s > 0; s >>= 1){
        if (tid < s) red[tid] += red[tid + s];
        __syncthreads();
    }
    const float inv = 1.0f / red[0];
    __syncthreads();

    for (int i = tid; i < len; i += 256){
        __half h, l;
        split2(buf[i] * inv, h, l);
        Ph[i] = h; Pl[i] = l;
    }
    // zero-pad to the 128-tile boundary so PV's diagonal tiles read zeros
    const int bound = ((q >> 7) + 1) << 7;
    const __half z = __float2half(0.f);
    for (int i = len + tid; i < bound; i += 256){ Ph[i] = z; Pl[i] = z; }
}

// ---------------- kernel 7: O = P @ V (triangular K range) ----------------
__global__ void __launch_bounds__(256, 1) k_pv(float* __restrict__ Out){
    const int dt = blockIdx.x, qt = blockIdx.y, b = blockIdx.z;
    extern __shared__ __align__(128) char smem[];
    uint32_t sm = smem_u32(smem);
    const int tid = threadIdx.x;
    float acc[2][8][4] = {};
    const int ktiles = (qt + 1) * (BM / BK);   // keys up to (qt+1)*128
    gemm_run(sm, tid,
             g_Ph  + (size_t)b*SS*SS, g_Pl  + (size_t)b*SS*SS, SS, qt*BM,
             g_Vth + (size_t)b*DD*SS, SS, dt*BN, ktiles, acc);
    const int lane = tid & 31, wid = tid >> 5, wm = wid & 3, wn = wid >> 2;
    const int r = lane >> 2, c = (lane & 3) * 2;
#pragma unroll
    for (int mi = 0; mi < 2; mi++)
#pragma unroll
        for (int ni = 0; ni < 8; ni++){
            int row = qt*BM + wm*32 + mi*16 + r;
            int col = dt*BN + wn*64 + ni*8 + c;
#pragma unroll
            for (int hrow = 0; hrow < 2; hrow++){
                size_t o = ((size_t)b*SS + row + hrow*8)*DD + col;
                *reinterpret_cast<float2*>(Out + o) =
                    make_float2(acc[mi][ni][hrow*2+0], acc[mi][ni][hrow*2+1]);
            }
        }
}

// ---------------- host ----------------
extern "C" void kernel_launch(void* const* d_in, const int* in_sizes, int n_in,
                              void* d_out, int out_size) {
    const float* x  = (const float*)d_in[0];
    const float* Q  = (const float*)d_in[1];
    const float* K  = (const float*)d_in[2];
    const float* V  = (const float*)d_in[3];
    float* out = (float*)d_out;

    cudaFuncSetAttribute(k_proj,   cudaFuncAttributeMaxDynamicSharedMemorySize, SMEM_BYTES);
    cudaFuncSetAttribute(k_scores, cudaFuncAttributeMaxDynamicSharedMemorySize, SMEM_BYTES);
    cudaFuncSetAttribute(k_pv,     cudaFuncAttributeMaxDynamicSharedMemorySize, SMEM_BYTES);

    k_split_x<<<(unsigned)((size_t)MTOT*DD/1024), 256>>>(x);
    k_split_w<<<dim3(DD/32, DD/32, 3), dim3(32, 8)>>>(Q, K, V);
    k_proj<<<dim3(DD/BN, MTOT/BM, 3), 256, SMEM_BYTES>>>();
    k_vtrans<<<dim3(DD/32, SS/32, BB), dim3(32, 8)>>>();
    k_scores<<<dim3(SS/BN, SS/BM, BB), 256, SMEM_BYTES>>>();
    k_softmax<<<dim3(SS, BB), 256>>>();
    k_pv<<<dim3(DD/BN, SS/BM, BB), 256, SMEM_BYTES>>>(out);
}

// round 7
// speedup vs baseline: 4.9831x; 1.2929x over previous
#include <cuda_runtime.h>
#include <cuda_fp16.h>
#include <cstdint>

#define BB 4
#define SS 4096
#define DD 1024
#define MTOT (BB*SS)

#define BM 128
#define BN 128
#define BK 32
#define TILE_B (128*64)             // 128 rows x 64 bytes (32 halfwords), swizzled
#define SMEM_BYTES 49152            // 48 KB per CTA -> 2 CTAs/SM

// ---------------- device scratch ----------------
__device__ __half g_xh [(size_t)MTOT*DD];
__device__ __half g_xl [(size_t)MTOT*DD];
__device__ __half g_Wth[(size_t)3*DD*DD];   // W^T hi: [z][n][k]
__device__ __half g_Qxh[(size_t)MTOT*DD];
__device__ __half g_Qxl[(size_t)MTOT*DD];
__device__ __half g_Kxh[(size_t)MTOT*DD];
__device__ float  g_Vx [(size_t)MTOT*DD];
__device__ __half g_Vth[(size_t)MTOT*DD];   // Vx^T hi: [b][d][s]
__device__ float  g_S  [(size_t)BB*SS*SS];
__device__ __half g_Ph [(size_t)BB*SS*SS];

// ---------------- asm helpers ----------------
__device__ __forceinline__ uint32_t smem_u32(const void* p){
    uint32_t a;
    asm("{ .reg .u64 t; cvta.to.shared.u64 t, %1; cvt.u32.u64 %0, t; }" : "=r"(a) : "l"(p));
    return a;
}
#define CPA(dst, src) asm volatile("cp.async.cg.shared.global [%0], [%1], 16;" :: "r"(dst), "l"(src))
#define CPC()  asm volatile("cp.async.commit_group;")

template<int N> __device__ __forceinline__ void cp_wait();
template<> __device__ __forceinline__ void cp_wait<0>(){ asm volatile("cp.async.wait_group 0;"); }
template<> __device__ __forceinline__ void cp_wait<1>(){ asm volatile("cp.async.wait_group 1;"); }
template<> __device__ __forceinline__ void cp_wait<2>(){ asm volatile("cp.async.wait_group 2;"); }

#define LDSM4(r0,r1,r2,r3,addr) \
    asm volatile("ldmatrix.sync.aligned.m8n8.x4.shared.b16 {%0,%1,%2,%3}, [%4];" \
        : "=r"(r0), "=r"(r1), "=r"(r2), "=r"(r3) : "r"(addr))

#define MMA(d, a, b) asm volatile( \
    "mma.sync.aligned.m16n8k16.row.col.f32.f16.f16.f32 " \
    "{%0,%1,%2,%3}, {%4,%5,%6,%7}, {%8,%9}, {%0,%1,%2,%3};" \
    : "+f"((d)[0]), "+f"((d)[1]), "+f"((d)[2]), "+f"((d)[3]) \
    : "r"((a)[0]), "r"((a)[1]), "r"((a)[2]), "r"((a)[3]), "r"((b)[0]), "r"((b)[1]))

__device__ __forceinline__ void split2(float v, __half& h, __half& l){
    h = __float2half(v);
    l = __float2half(v - __half2float(h));
}

// swizzled byte offset within a tile: row r (0..127), 16B chunk c (0..3)
__device__ __forceinline__ uint32_t swz(uint32_t r, uint32_t c){
    return r*64u + ((c ^ (r & 3u)) * 16u);
}

// ---------------- stage load (cp.async, swizzled) ----------------
template<bool SA>
__device__ __forceinline__ void load_stage(uint32_t sm,
    const __half* Ah, const __half* Al, size_t lda, int r0a,
    const __half* Bh, size_t ldb, int r0b,
    int k0, int tid)
{
    constexpr int NT = SA ? 3 : 2;
#pragma unroll
    for (int i = 0; i < 2; i++){
        int id = tid + i*256;                 // 0..511
        uint32_t r = (uint32_t)(id >> 2), c = (uint32_t)(id & 3);
        uint32_t so = swz(r, c);
        size_t goa = (size_t)(r0a + (int)r)*lda + k0 + c*8;
        size_t gob = (size_t)(r0b + (int)r)*ldb + k0 + c*8;
        CPA(sm + so, Ah + goa);
        if (SA) CPA(sm + TILE_B + so, Al + goa);
        CPA(sm + (NT-1)*TILE_B + so, Bh + gob);
    }
}

// ---------------- stage compute ----------------
template<bool SA>
__device__ __forceinline__ void compute_stage(uint32_t sm, int lane, int wm, int wn,
                                              float acc[2][8][4])
{
    const uint32_t aAh = sm;
    const uint32_t aAl = sm + TILE_B;
    const uint32_t aBh = sm + (SA ? 2 : 1)*TILE_B;
    const int ar = lane & 15;
    const int ac = lane >> 4;               // A chunk sub-index (0/1)
    const int br = (lane & 7) | ((lane >> 4) << 3);
    const int bc = (lane >> 3) & 1;         // B chunk sub-index (0/1)
#pragma unroll
    for (int ks = 0; ks < 2; ks++){
        uint32_t ah[2][4], al[2][4], bh[8][2];
#pragma unroll
        for (int mi = 0; mi < 2; mi++){
            uint32_t r = (uint32_t)(wm*32 + mi*16 + ar);
            uint32_t off = swz(r, (uint32_t)(ks*2 + ac));
            LDSM4(ah[mi][0], ah[mi][1], ah[mi][2], ah[mi][3], aAh + off);
            if (SA) LDSM4(al[mi][0], al[mi][1], al[mi][2], al[mi][3], aAl + off);
        }
#pragma unroll
        for (int np = 0; np < 4; np++){
            uint32_t r = (uint32_t)(wn*64 + np*16 + br);
            uint32_t off = swz(r, (uint32_t)(ks*2 + bc));
            LDSM4(bh[2*np][0], bh[2*np][1], bh[2*np+1][0], bh[2*np+1][1], aBh + off);
        }
#pragma unroll
        for (int mi = 0; mi < 2; mi++)
#pragma unroll
            for (int ni = 0; ni < 8; ni++){
                MMA(acc[mi][ni], ah[mi], bh[ni]);
                if (SA) MMA(acc[mi][ni], al[mi], bh[ni]);
            }
    }
}

// ---------------- GEMM mainloop (NST-stage pipeline, 1 sync/iter) ----------------
template<bool SA, int NST>
__device__ __forceinline__ void gemm_run(uint32_t sm, int tid,
    const __half* Ah, const __half* Al, size_t lda, int r0a,
    const __half* Bh, size_t ldb, int r0b,
    int ktiles, float acc[2][8][4])
{
    constexpr int STAGE = (SA ? 3 : 2) * TILE_B;
    const int lane = tid & 31, wid = tid >> 5;
    const int wm = wid & 3, wn = wid >> 2;
    const int kend = ktiles * BK;

    // prologue: prefetch NST-1 stages
#pragma unroll
    for (int s = 0; s < NST - 1; s++){
        int k = min(s * BK, kend - BK);
        load_stage<SA>(sm + s*STAGE, Ah, Al, lda, r0a, Bh, ldb, r0b, k, tid);
        CPC();
    }

    int buf = 0;
    int nxt = NST - 1;
    for (int kt = 0; kt < ktiles; kt++){
        cp_wait<NST-2>();       // stage kt complete
        __syncthreads();        // buffer nxt free (all warps done with it)
        {
            int k = min((kt + NST - 1) * BK, kend - BK);   // clamped prefetch
            load_stage<SA>(sm + nxt*STAGE, Ah, Al, lda, r0a, Bh, ldb, r0b, k, tid);
            CPC();
        }
        compute_stage<SA>(sm + buf*STAGE, lane, wm, wn, acc);
        buf = (buf + 1 == NST) ? 0 : buf + 1;
        nxt = (nxt + 1 == NST) ? 0 : nxt + 1;
    }
}

// ---------------- kernel 1: split x -> fp16 hi/lo ----------------
__global__ void k_split_x(const float* __restrict__ x){
    size_t i = ((size_t)blockIdx.x * 256 + threadIdx.x) * 4;
    float4 v = *reinterpret_cast<const float4*>(x + i);
    __half h[4], l[4];
    split2(v.x, h[0], l[0]); split2(v.y, h[1], l[1]);
    split2(v.z, h[2], l[2]); split2(v.w, h[3], l[3]);
    __half2 h01{h[0],h[1]}, h23{h[2],h[3]}, l01{l[0],l[1]}, l23{l[2],l[3]};
    *reinterpret_cast<__half2*>(g_xh + i)     = h01;
    *reinterpret_cast<__half2*>(g_xh + i + 2) = h23;
    *reinterpret_cast<__half2*>(g_xl + i)     = l01;
    *reinterpret_cast<__half2*>(g_xl + i + 2) = l23;
}

// ---------------- kernel 2: transpose weights (hi only) ----------------
__global__ void k_split_w(const float* __restrict__ Wq,
                          const float* __restrict__ Wk,
                          const float* __restrict__ Wv){
    const int z = blockIdx.z;
    const float* W = (z == 0) ? Wq : (z == 1) ? Wk : Wv;
    __half* H = g_Wth + (size_t)z*DD*DD;
    __shared__ float t[32][33];
    int tx = threadIdx.x, ty = threadIdx.y;
    int kb = blockIdx.y * 32, nb = blockIdx.x * 32;
#pragma unroll
    for (int j = 0; j < 4; j++)
        t[ty + j*8][tx] = W[(size_t)(kb + ty + j*8)*DD + nb + tx];
    __syncthreads();
#pragma unroll
    for (int j = 0; j < 4; j++){
        int n = nb + ty + j*8, k = kb + tx;
        H[(size_t)n*DD + k] = __float2half(t[tx][ty + j*8]);
    }
}

// ---------------- kernel 3: projections ----------------
__global__ void __launch_bounds__(256, 2) k_proj(){
    extern __shared__ __align__(128) char smem[];
    uint32_t sm = smem_u32(smem);
    const int tid = threadIdx.x;
    const int z = blockIdx.z, m0 = blockIdx.y*BM, n0 = blockIdx.x*BN;
    float acc[2][8][4] = {};
    gemm_run<true,2>(sm, tid, g_xh, g_xl, DD, m0,
                     g_Wth + (size_t)z*DD*DD, DD, n0, DD/BK, acc);
    const int lane = tid & 31, wid = tid >> 5, wm = wid & 3, wn = wid >> 2;
    const int r = lane >> 2, c = (lane & 3) * 2;
#pragma unroll
    for (int mi = 0; mi < 2; mi++)
#pragma unroll
        for (int ni = 0; ni < 8; ni++){
            int row = m0 + wm*32 + mi*16 + r;
            int col = n0 + wn*64 + ni*8 + c;
#pragma unroll
            for (int hrow = 0; hrow < 2; hrow++){
                float v0 = acc[mi][ni][hrow*2 + 0];
                float v1 = acc[mi][ni][hrow*2 + 1];
                size_t o = (size_t)(row + hrow*8)*DD + col;
                if (z == 0){
                    __half h0,l0,h1,l1;
                    split2(v0, h0, l0); split2(v1, h1, l1);
                    __half2 hp{h0,h1}, lp{l0,l1};
                    *reinterpret_cast<__half2*>(g_Qxh + o) = hp;
                    *reinterpret_cast<__half2*>(g_Qxl + o) = lp;
                } else if (z == 1){
                    __half2 hp{__float2half(v0), __float2half(v1)};
                    *reinterpret_cast<__half2*>(g_Kxh + o) = hp;
                } else {
                    *reinterpret_cast<float2*>(g_Vx + o) = make_float2(v0, v1);
                }
            }
        }
}

// ---------------- kernel 4: transpose Vx (hi only) ----------------
__global__ void k_vtrans(){
    const int b = blockIdx.z;
    const float* Vx = g_Vx + (size_t)b*SS*DD;
    __half* H = g_Vth + (size_t)b*DD*SS;
    __shared__ float t[32][33];
    int tx = threadIdx.x, ty = threadIdx.y;
    int s0 = blockIdx.y * 32, d0 = blockIdx.x * 32;
#pragma unroll
    for (int j = 0; j < 4; j++)
        t[ty + j*8][tx] = Vx[(size_t)(s0 + ty + j*8)*DD + d0 + tx];
    __syncthreads();
#pragma unroll
    for (int j = 0; j < 4; j++){
        int d = d0 + ty + j*8, s = s0 + tx;
        H[(size_t)d*SS + s] = __float2half(t[tx][ty + j*8]);
    }
}

// ---------------- kernel 5: scores (lower-tri tiles) ----------------
__global__ void __launch_bounds__(256, 2) k_scores(){
    const int kt = blockIdx.x, qt = blockIdx.y, b = blockIdx.z;
    if (kt > qt) return;
    extern __shared__ __align__(128) char smem[];
    uint32_t sm = smem_u32(smem);
    const int tid = threadIdx.x;
    float acc[2][8][4] = {};
    gemm_run<true,2>(sm, tid,
                     g_Qxh + (size_t)b*SS*DD, g_Qxl + (size_t)b*SS*DD, DD, qt*BM,
                     g_Kxh + (size_t)b*SS*DD, DD, kt*BN, DD/BK, acc);
    const int lane = tid & 31, wid = tid >> 5, wm = wid & 3, wn = wid >> 2;
    const int r = lane >> 2, c = (lane & 3) * 2;
    float* Sp = g_S + (size_t)b*SS*SS;
#pragma unroll
    for (int mi = 0; mi < 2; mi++)
#pragma unroll
        for (int ni = 0; ni < 8; ni++){
            int row = qt*BM + wm*32 + mi*16 + r;
            int col = kt*BN + wn*64 + ni*8 + c;
#pragma unroll
            for (int hrow = 0; hrow < 2; hrow++){
                size_t o = (size_t)(row + hrow*8)*SS + col;
                *reinterpret_cast<float2*>(Sp + o) =
                    make_float2(acc[mi][ni][hrow*2+0]*0.03125f,
                                acc[mi][ni][hrow*2+1]*0.03125f);
            }
        }
}

// ---------------- kernel 6: softmax -> fp16 probs (hi only) + pad ----------------
__global__ void k_softmax(){
    const int q = blockIdx.x;
    const int b = blockIdx.y;
    const float* row = g_S + (size_t)b*SS*SS + (size_t)q*SS;
    __half* Ph = g_Ph + (size_t)b*SS*SS + (size_t)q*SS;
    const int len = q + 1;

    __shared__ float buf[SS];
    __shared__ float red[256];
    const int tid = threadIdx.x;

    float mx = -1e30f;
    for (int i = tid; i < len; i += 256){
        float v = row[i];
        buf[i] = v;
        mx = fmaxf(mx, v);
    }
    red[tid] = mx;
    __syncthreads();
    for (int s = 128; s > 0; s >>= 1){
        if (tid < s) red[tid] = fmaxf(red[tid], red[tid + s]);
        __syncthreads();
    }
    mx = red[0];
    __syncthreads();

    float sum = 0.f;
    for (int i = tid; i < len; i += 256){
        float e = __expf(buf[i] - mx);
        buf[i] = e;
        sum += e;
    }
    red[tid] = sum;
    __syncthreads();
    for (int s = 128; s > 0; s >>= 1){
        if (tid < s) red[tid] += red[tid + s];
        __syncthreads();
    }
    const float inv = 1.0f / red[0];
    __syncthreads();

    for (int i = tid; i < len; i += 256)
        Ph[i] = __float2half(buf[i] * inv);
    // zero-pad to the 128-tile boundary so PV's diagonal tiles read zeros
    const int bound = ((q >> 7) + 1) << 7;
    const __half z = __float2half(0.f);
    for (int i = len + tid; i < bound; i += 256) Ph[i] = z;
}

// ---------------- kernel 7: O = P @ V (triangular K range, 1-pass) ----------------
__global__ void __launch_bounds__(256, 2) k_pv(float* __restrict__ Out){
    const int dt = blockIdx.x, qt = blockIdx.y, b = blockIdx.z;
    extern __shared__ __align__(128) char smem[];
    uint32_t sm = smem_u32(smem);
    const int tid = threadIdx.x;
    float acc[2][8][4] = {};
    const int ktiles = (qt + 1) * (BM / BK);   // keys up to (qt+1)*128
    gemm_run<false,3>(sm, tid,
                      g_Ph  + (size_t)b*SS*SS, nullptr, SS, qt*BM,
                      g_Vth + (size_t)b*DD*SS, SS, dt*BN, ktiles, acc);
    const int lane = tid & 31, wid = tid >> 5, wm = wid & 3, wn = wid >> 2;
    const int r = lane >> 2, c = (lane & 3) * 2;
#pragma unroll
    for (int mi = 0; mi < 2; mi++)
#pragma unroll
        for (int ni = 0; ni < 8; ni++){
            int row = qt*BM + wm*32 + mi*16 + r;
            int col = dt*BN + wn*64 + ni*8 + c;
#pragma unroll
            for (int hrow = 0; hrow < 2; hrow++){
                size_t o = ((size_t)b*SS + row + hrow*8)*DD + col;
                *reinterpret_cast<float2*>(Out + o) =
                    make_float2(acc[mi][ni][hrow*2+0], acc[mi][ni][hrow*2+1]);
            }
        }
}

// ---------------- host ----------------
extern "C" void kernel_launch(void* const* d_in, const int* in_sizes, int n_in,
                              void* d_out, int out_size) {
    const float* x  = (const float*)d_in[0];
    const float* Q  = (const float*)d_in[1];
    const float* K  = (const float*)d_in[2];
    const float* V  = (const float*)d_in[3];
    float* out = (float*)d_out;

    cudaFuncSetAttribute(k_proj,   cudaFuncAttributeMaxDynamicSharedMemorySize, SMEM_BYTES);
    cudaFuncSetAttribute(k_scores, cudaFuncAttributeMaxDynamicSharedMemorySize, SMEM_BYTES);
    cudaFuncSetAttribute(k_pv,     cudaFuncAttributeMaxDynamicSharedMemorySize, SMEM_BYTES);

    k_split_x<<<(unsigned)((size_t)MTOT*DD/1024), 256>>>(x);
    k_split_w<<<dim3(DD/32, DD/32, 3), dim3(32, 8)>>>(Q, K, V);
    k_proj<<<dim3(DD/BN, MTOT/BM, 3), 256, SMEM_BYTES>>>();
    k_vtrans<<<dim3(DD/32, SS/32, BB), dim3(32, 8)>>>();
    k_scores<<<dim3(SS/BN, SS/BM, BB), 256, SMEM_BYTES>>>();
    k_softmax<<<dim3(SS, BB), 256>>>();
    k_pv<<<dim3(DD/BN, SS/BM, BB), 256, SMEM_BYTES>>>(out);
}

// round 8
// speedup vs baseline: 5.4398x; 1.0916x over previous
#include <cuda_runtime.h>
#include <cuda_fp16.h>
#include <cstdint>

#define BB 4
#define SS 4096
#define DD 1024
#define MTOT (BB*SS)

#define BM 128
#define BN 128
#define BK 32
#define TILE_B (128*64)             // 128 rows x 64 bytes (32 halfwords), swizzled
#define SMEM_BYTES 49152            // 48 KB per CTA -> 2 CTAs/SM

// ---------------- device scratch ----------------
__device__ __half g_xh [(size_t)MTOT*DD];
__device__ __half g_xl [(size_t)MTOT*DD];
__device__ __half g_Wth[(size_t)3*DD*DD];   // W^T hi: [z][n][k]
__device__ __half g_Qxh[(size_t)MTOT*DD];
__device__ __half g_Qxl[(size_t)MTOT*DD];
__device__ __half g_Kxh[(size_t)MTOT*DD];
__device__ float  g_Vx [(size_t)MTOT*DD];
__device__ __half g_Vth[(size_t)MTOT*DD];   // Vx^T hi: [b][d][s]
__device__ float  g_S  [(size_t)BB*SS*SS];
__device__ __half g_Ph [(size_t)BB*SS*SS];

// ---------------- asm helpers ----------------
__device__ __forceinline__ uint32_t smem_u32(const void* p){
    uint32_t a;
    asm("{ .reg .u64 t; cvta.to.shared.u64 t, %1; cvt.u32.u64 %0, t; }" : "=r"(a) : "l"(p));
    return a;
}
#define CPA(dst, src) asm volatile("cp.async.cg.shared.global [%0], [%1], 16;" :: "r"(dst), "l"(src))
#define CPC()  asm volatile("cp.async.commit_group;")

template<int N> __device__ __forceinline__ void cp_wait();
template<> __device__ __forceinline__ void cp_wait<0>(){ asm volatile("cp.async.wait_group 0;"); }
template<> __device__ __forceinline__ void cp_wait<1>(){ asm volatile("cp.async.wait_group 1;"); }
template<> __device__ __forceinline__ void cp_wait<2>(){ asm volatile("cp.async.wait_group 2;"); }

#define LDSM4(r0,r1,r2,r3,addr) \
    asm volatile("ldmatrix.sync.aligned.m8n8.x4.shared.b16 {%0,%1,%2,%3}, [%4];" \
        : "=r"(r0), "=r"(r1), "=r"(r2), "=r"(r3) : "r"(addr))

#define MMA(d, a, b) asm volatile( \
    "mma.sync.aligned.m16n8k16.row.col.f32.f16.f16.f32 " \
    "{%0,%1,%2,%3}, {%4,%5,%6,%7}, {%8,%9}, {%0,%1,%2,%3};" \
    : "+f"((d)[0]), "+f"((d)[1]), "+f"((d)[2]), "+f"((d)[3]) \
    : "r"((a)[0]), "r"((a)[1]), "r"((a)[2]), "r"((a)[3]), "r"((b)[0]), "r"((b)[1]))

__device__ __forceinline__ void split2(float v, __half& h, __half& l){
    h = __float2half(v);
    l = __float2half(v - __half2float(h));
}

// swizzled byte offset within a tile: row r (0..127), 16B chunk c (0..3)
__device__ __forceinline__ uint32_t swz(uint32_t r, uint32_t c){
    return r*64u + ((c ^ (r & 3u)) * 16u);
}

// ---------------- stage load (cp.async, swizzled) ----------------
template<bool SA>
__device__ __forceinline__ void load_stage(uint32_t sm,
    const __half* Ah, const __half* Al, size_t lda, int r0a,
    const __half* Bh, size_t ldb, int r0b,
    int k0, int tid)
{
    constexpr int NT = SA ? 3 : 2;
#pragma unroll
    for (int i = 0; i < 2; i++){
        int id = tid + i*256;                 // 0..511
        uint32_t r = (uint32_t)(id >> 2), c = (uint32_t)(id & 3);
        uint32_t so = swz(r, c);
        size_t goa = (size_t)(r0a + (int)r)*lda + k0 + c*8;
        size_t gob = (size_t)(r0b + (int)r)*ldb + k0 + c*8;
        CPA(sm + so, Ah + goa);
        if (SA) CPA(sm + TILE_B + so, Al + goa);
        CPA(sm + (NT-1)*TILE_B + so, Bh + gob);
    }
}

// ---------------- stage compute ----------------
template<bool SA>
__device__ __forceinline__ void compute_stage(uint32_t sm, int lane, int wm, int wn,
                                              float acc[2][8][4])
{
    const uint32_t aAh = sm;
    const uint32_t aAl = sm + TILE_B;
    const uint32_t aBh = sm + (SA ? 2 : 1)*TILE_B;
    const int ar = lane & 15;
    const int ac = lane >> 4;               // A chunk sub-index (0/1)
    const int br = (lane & 7) | ((lane >> 4) << 3);
    const int bc = (lane >> 3) & 1;         // B chunk sub-index (0/1)
#pragma unroll
    for (int ks = 0; ks < 2; ks++){
        uint32_t ah[2][4], al[2][4], bh[8][2];
#pragma unroll
        for (int mi = 0; mi < 2; mi++){
            uint32_t r = (uint32_t)(wm*32 + mi*16 + ar);
            uint32_t off = swz(r, (uint32_t)(ks*2 + ac));
            LDSM4(ah[mi][0], ah[mi][1], ah[mi][2], ah[mi][3], aAh + off);
            if (SA) LDSM4(al[mi][0], al[mi][1], al[mi][2], al[mi][3], aAl + off);
        }
#pragma unroll
        for (int np = 0; np < 4; np++){
            uint32_t r = (uint32_t)(wn*64 + np*16 + br);
            uint32_t off = swz(r, (uint32_t)(ks*2 + bc));
            LDSM4(bh[2*np][0], bh[2*np][1], bh[2*np+1][0], bh[2*np+1][1], aBh + off);
        }
#pragma unroll
        for (int mi = 0; mi < 2; mi++)
#pragma unroll
            for (int ni = 0; ni < 8; ni++){
                MMA(acc[mi][ni], ah[mi], bh[ni]);
                if (SA) MMA(acc[mi][ni], al[mi], bh[ni]);
            }
    }
}

// ---------------- GEMM mainloop (NST-stage pipeline, 1 sync/iter) ----------------
template<bool SA, int NST>
__device__ __forceinline__ void gemm_run(uint32_t sm, int tid,
    const __half* Ah, const __half* Al, size_t lda, int r0a,
    const __half* Bh, size_t ldb, int r0b,
    int ktiles, float acc[2][8][4])
{
    constexpr int STAGE = (SA ? 3 : 2) * TILE_B;
    const int lane = tid & 31, wid = tid >> 5;
    const int wm = wid & 3, wn = wid >> 2;
    const int kend = ktiles * BK;

    // prologue: prefetch NST-1 stages
#pragma unroll
    for (int s = 0; s < NST - 1; s++){
        int k = min(s * BK, kend - BK);
        load_stage<SA>(sm + s*STAGE, Ah, Al, lda, r0a, Bh, ldb, r0b, k, tid);
        CPC();
    }

    int buf = 0;
    int nxt = NST - 1;
    for (int kt = 0; kt < ktiles; kt++){
        cp_wait<NST-2>();       // stage kt complete
        __syncthreads();        // buffer nxt free (all warps done with it)
        {
            int k = min((kt + NST - 1) * BK, kend - BK);   // clamped prefetch
            load_stage<SA>(sm + nxt*STAGE, Ah, Al, lda, r0a, Bh, ldb, r0b, k, tid);
            CPC();
        }
        compute_stage<SA>(sm + buf*STAGE, lane, wm, wn, acc);
        buf = (buf + 1 == NST) ? 0 : buf + 1;
        nxt = (nxt + 1 == NST) ? 0 : nxt + 1;
    }
}

// ---------------- kernel 1: split x -> fp16 hi/lo ----------------
__global__ void k_split_x(const float* __restrict__ x){
    size_t i = ((size_t)blockIdx.x * 256 + threadIdx.x) * 4;
    float4 v = *reinterpret_cast<const float4*>(x + i);
    __half h[4], l[4];
    split2(v.x, h[0], l[0]); split2(v.y, h[1], l[1]);
    split2(v.z, h[2], l[2]); split2(v.w, h[3], l[3]);
    __half2 h01{h[0],h[1]}, h23{h[2],h[3]}, l01{l[0],l[1]}, l23{l[2],l[3]};
    *reinterpret_cast<__half2*>(g_xh + i)     = h01;
    *reinterpret_cast<__half2*>(g_xh + i + 2) = h23;
    *reinterpret_cast<__half2*>(g_xl + i)     = l01;
    *reinterpret_cast<__half2*>(g_xl + i + 2) = l23;
}

// ---------------- kernel 2: transpose weights (hi only) ----------------
__global__ void k_split_w(const float* __restrict__ Wq,
                          const float* __restrict__ Wk,
                          const float* __restrict__ Wv){
    const int z = blockIdx.z;
    const float* W = (z == 0) ? Wq : (z == 1) ? Wk : Wv;
    __half* H = g_Wth + (size_t)z*DD*DD;
    __shared__ float t[32][33];
    int tx = threadIdx.x, ty = threadIdx.y;
    int kb = blockIdx.y * 32, nb = blockIdx.x * 32;
#pragma unroll
    for (int j = 0; j < 4; j++)
        t[ty + j*8][tx] = W[(size_t)(kb + ty + j*8)*DD + nb + tx];
    __syncthreads();
#pragma unroll
    for (int j = 0; j < 4; j++){
        int n = nb + ty + j*8, k = kb + tx;
        H[(size_t)n*DD + k] = __float2half(t[tx][ty + j*8]);
    }
}

// ---------------- kernel 3a: Q projection (2-pass split) ----------------
__global__ void __launch_bounds__(256, 2) k_proj_q(){
    extern __shared__ __align__(128) char smem[];
    uint32_t sm = smem_u32(smem);
    const int tid = threadIdx.x;
    const int m0 = blockIdx.y*BM, n0 = blockIdx.x*BN;
    float acc[2][8][4] = {};
    gemm_run<true,2>(sm, tid, g_xh, g_xl, DD, m0, g_Wth, DD, n0, DD/BK, acc);
    const int lane = tid & 31, wid = tid >> 5, wm = wid & 3, wn = wid >> 2;
    const int r = lane >> 2, c = (lane & 3) * 2;
#pragma unroll
    for (int mi = 0; mi < 2; mi++)
#pragma unroll
        for (int ni = 0; ni < 8; ni++){
            int row = m0 + wm*32 + mi*16 + r;
            int col = n0 + wn*64 + ni*8 + c;
#pragma unroll
            for (int hrow = 0; hrow < 2; hrow++){
                float v0 = acc[mi][ni][hrow*2 + 0];
                float v1 = acc[mi][ni][hrow*2 + 1];
                size_t o = (size_t)(row + hrow*8)*DD + col;
                __half h0,l0,h1,l1;
                split2(v0, h0, l0); split2(v1, h1, l1);
                __half2 hp{h0,h1}, lp{l0,l1};
                *reinterpret_cast<__half2*>(g_Qxh + o) = hp;
                *reinterpret_cast<__half2*>(g_Qxl + o) = lp;
            }
        }
}

// ---------------- kernel 3b: K/V projections (1-pass; rounded to fp16 anyway) --
__global__ void __launch_bounds__(256, 2) k_proj_kv(){
    extern __shared__ __align__(128) char smem[];
    uint32_t sm = smem_u32(smem);
    const int tid = threadIdx.x;
    const int z = blockIdx.z;                 // 0 -> K, 1 -> V
    const int m0 = blockIdx.y*BM, n0 = blockIdx.x*BN;
    float acc[2][8][4] = {};
    gemm_run<false,3>(sm, tid, g_xh, nullptr, DD, m0,
                      g_Wth + (size_t)(z+1)*DD*DD, DD, n0, DD/BK, acc);
    const int lane = tid & 31, wid = tid >> 5, wm = wid & 3, wn = wid >> 2;
    const int r = lane >> 2, c = (lane & 3) * 2;
#pragma unroll
    for (int mi = 0; mi < 2; mi++)
#pragma unroll
        for (int ni = 0; ni < 8; ni++){
            int row = m0 + wm*32 + mi*16 + r;
            int col = n0 + wn*64 + ni*8 + c;
#pragma unroll
            for (int hrow = 0; hrow < 2; hrow++){
                float v0 = acc[mi][ni][hrow*2 + 0];
                float v1 = acc[mi][ni][hrow*2 + 1];
                size_t o = (size_t)(row + hrow*8)*DD + col;
                if (z == 0){
                    __half2 hp{__float2half(v0), __float2half(v1)};
                    *reinterpret_cast<__half2*>(g_Kxh + o) = hp;
                } else {
                    *reinterpret_cast<float2*>(g_Vx + o) = make_float2(v0, v1);
                }
            }
        }
}

// ---------------- kernel 4: transpose Vx (hi only) ----------------
__global__ void k_vtrans(){
    const int b = blockIdx.z;
    const float* Vx = g_Vx + (size_t)b*SS*DD;
    __half* H = g_Vth + (size_t)b*DD*SS;
    __shared__ float t[32][33];
    int tx = threadIdx.x, ty = threadIdx.y;
    int s0 = blockIdx.y * 32, d0 = blockIdx.x * 32;
#pragma unroll
    for (int j = 0; j < 4; j++)
        t[ty + j*8][tx] = Vx[(size_t)(s0 + ty + j*8)*DD + d0 + tx];
    __syncthreads();
#pragma unroll
    for (int j = 0; j < 4; j++){
        int d = d0 + ty + j*8, s = s0 + tx;
        H[(size_t)d*SS + s] = __float2half(t[tx][ty + j*8]);
    }
}

// ---------------- kernel 5: scores (lower-tri tiles) ----------------
__global__ void __launch_bounds__(256, 2) k_scores(){
    const int kt = blockIdx.x, qt = blockIdx.y, b = blockIdx.z;
    if (kt > qt) return;
    extern __shared__ __align__(128) char smem[];
    uint32_t sm = smem_u32(smem);
    const int tid = threadIdx.x;
    float acc[2][8][4] = {};
    gemm_run<true,2>(sm, tid,
                     g_Qxh + (size_t)b*SS*DD, g_Qxl + (size_t)b*SS*DD, DD, qt*BM,
                     g_Kxh + (size_t)b*SS*DD, DD, kt*BN, DD/BK, acc);
    const int lane = tid & 31, wid = tid >> 5, wm = wid & 3, wn = wid >> 2;
    const int r = lane >> 2, c = (lane & 3) * 2;
    float* Sp = g_S + (size_t)b*SS*SS;
#pragma unroll
    for (int mi = 0; mi < 2; mi++)
#pragma unroll
        for (int ni = 0; ni < 8; ni++){
            int row = qt*BM + wm*32 + mi*16 + r;
            int col = kt*BN + wn*64 + ni*8 + c;
#pragma unroll
            for (int hrow = 0; hrow < 2; hrow++){
                size_t o = (size_t)(row + hrow*8)*SS + col;
                *reinterpret_cast<float2*>(Sp + o) =
                    make_float2(acc[mi][ni][hrow*2+0]*0.03125f,
                                acc[mi][ni][hrow*2+1]*0.03125f);
            }
        }
}

// ---------------- kernel 6: softmax -> fp16 probs (hi only) + pad ----------------
__global__ void k_softmax(){
    const int q = blockIdx.x;
    const int b = blockIdx.y;
    const float* row = g_S + (size_t)b*SS*SS + (size_t)q*SS;
    __half* Ph = g_Ph + (size_t)b*SS*SS + (size_t)q*SS;
    const int len = q + 1;

    __shared__ float buf[SS];
    __shared__ float red[256];
    const int tid = threadIdx.x;

    float mx = -1e30f;
    for (int i = tid; i < len; i += 256){
        float v = row[i];
        buf[i] = v;
        mx = fmaxf(mx, v);
    }
    red[tid] = mx;
    __syncthreads();
    for (int s = 128; s > 0; s >>= 1){
        if (tid < s) red[tid] = fmaxf(red[tid], red[tid + s]);
        __syncthreads();
    }
    mx = red[0];
    __syncthreads();

    float sum = 0.f;
    for (int i = tid; i < len; i += 256){
        float e = __expf(buf[i] - mx);
        buf[i] = e;
        sum += e;
    }
    red[tid] = sum;
    __syncthreads();
    for (int s = 128; s > 0; s >>= 1){
        if (tid < s) red[tid] += red[tid + s];
        __syncthreads();
    }
    const float inv = 1.0f / red[0];
    __syncthreads();

    for (int i = tid; i < len; i += 256)
        Ph[i] = __float2half(buf[i] * inv);
    // zero-pad to the 128-tile boundary so PV's diagonal tiles read zeros
    const int bound = ((q >> 7) + 1) << 7;
    const __half z = __float2half(0.f);
    for (int i = len + tid; i < bound; i += 256) Ph[i] = z;
}

// ---------------- kernel 7: O = P @ V (triangular K range, 1-pass) ----------------
__global__ void __launch_bounds__(256, 2) k_pv(float* __restrict__ Out){
    const int dt = blockIdx.x, qt = blockIdx.y, b = blockIdx.z;
    extern __shared__ __align__(128) char smem[];
    uint32_t sm = smem_u32(smem);
    const int tid = threadIdx.x;
    float acc[2][8][4] = {};
    const int ktiles = (qt + 1) * (BM / BK);   // keys up to (qt+1)*128
    gemm_run<false,3>(sm, tid,
                      g_Ph  + (size_t)b*SS*SS, nullptr, SS, qt*BM,
                      g_Vth + (size_t)b*DD*SS, SS, dt*BN, ktiles, acc);
    const int lane = tid & 31, wid = tid >> 5, wm = wid & 3, wn = wid >> 2;
    const int r = lane >> 2, c = (lane & 3) * 2;
#pragma unroll
    for (int mi = 0; mi < 2; mi++)
#pragma unroll
        for (int ni = 0; ni < 8; ni++){
            int row = qt*BM + wm*32 + mi*16 + r;
            int col = dt*BN + wn*64 + ni*8 + c;
#pragma unroll
            for (int hrow = 0; hrow < 2; hrow++){
                size_t o = ((size_t)b*SS + row + hrow*8)*DD + col;
                *reinterpret_cast<float2*>(Out + o) =
                    make_float2(acc[mi][ni][hrow*2+0], acc[mi][ni][hrow*2+1]);
            }
        }
}

// ---------------- host ----------------
extern "C" void kernel_launch(void* const* d_in, const int* in_sizes, int n_in,
                              void* d_out, int out_size) {
    const float* x  = (const float*)d_in[0];
    const float* Q  = (const float*)d_in[1];
    const float* K  = (const float*)d_in[2];
    const float* V  = (const float*)d_in[3];
    float* out = (float*)d_out;

    cudaFuncSetAttribute(k_proj_q,  cudaFuncAttributeMaxDynamicSharedMemorySize, SMEM_BYTES);
    cudaFuncSetAttribute(k_proj_kv, cudaFuncAttributeMaxDynamicSharedMemorySize, SMEM_BYTES);
    cudaFuncSetAttribute(k_scores,  cudaFuncAttributeMaxDynamicSharedMemorySize, SMEM_BYTES);
    cudaFuncSetAttribute(k_pv,      cudaFuncAttributeMaxDynamicSharedMemorySize, SMEM_BYTES);

    k_split_x<<<(unsigned)((size_t)MTOT*DD/1024), 256>>>(x);
    k_split_w<<<dim3(DD/32, DD/32, 3), dim3(32, 8)>>>(Q, K, V);
    k_proj_q <<<dim3(DD/BN, MTOT/BM),    256, SMEM_BYTES>>>();
    k_proj_kv<<<dim3(DD/BN, MTOT/BM, 2), 256, SMEM_BYTES>>>();
    k_vtrans<<<dim3(DD/32, SS/32, BB), dim3(32, 8)>>>();
    k_scores<<<dim3(SS/BN, SS/BM, BB), 256, SMEM_BYTES>>>();
    k_softmax<<<dim3(SS, BB), 256>>>();
    k_pv<<<dim3(DD/BN, SS/BM, BB), 256, SMEM_BYTES>>>(out);
}